// round 1
// baseline (speedup 1.0000x reference)
#include <cuda_runtime.h>
#include <cuda_bf16.h>
#include <cstdint>

// ---------------- problem constants ----------------
constexpr int Bsz   = 16;
constexpr int Hdim  = 112;
constexpr int Wdim  = 112;
constexpr int Cc    = 128;
constexpr int HEADS = 4;
constexpr int HD    = 32;      // head dim
constexpr int WS    = 7;
constexpr int L     = Hdim * Wdim;        // 12544
constexpr int T     = Bsz * L;            // 200704 tokens
constexpr int NTOK  = WS * WS;            // 49
constexpr int WPB   = (Hdim / WS) * (Wdim / WS);  // 256 windows per batch
constexpr int NWIN  = Bsz * WPB;          // 4096
constexpr int MLPH  = 512;
constexpr float SCALE = 0.17677669529663687f;  // 1/sqrt(32)
constexpr float EPS   = 1e-5f;

// ---------------- device scratch (static, no allocations) ----------------
__device__ __align__(16) __nv_bfloat16 g_xn[T * Cc];     // LN(x), window order
__device__ __align__(16) __nv_bfloat16 g_vn[T * Cc];     // LN(v), window order
__device__ __align__(16) __nv_bfloat16 g_q [T * Cc];     // q*scale, window order
__device__ __align__(16) __nv_bfloat16 g_k [T * Cc];
__device__ __align__(16) __nv_bfloat16 g_v [T * Cc];
__device__ __align__(16) __nv_bfloat16 g_ao[T * Cc];     // attention out, window order
__device__ __align__(16) float         g_xo[T * Cc];     // x + proj, token order (fp32)
__device__ __align__(16) __nv_bfloat16 g_xon[T * Cc];    // LN2(xo), token order
__device__ __align__(16) __nv_bfloat16 g_h1[(size_t)T * MLPH]; // gelu(fc1)
// bf16 weights
__device__ __align__(16) __nv_bfloat16 g_qw [Cc * Cc];
__device__ __align__(16) __nv_bfloat16 g_kvw[2 * Cc * Cc];
__device__ __align__(16) __nv_bfloat16 g_pw [Cc * Cc];
__device__ __align__(16) __nv_bfloat16 g_f1w[MLPH * Cc];
__device__ __align__(16) __nv_bfloat16 g_f2w[Cc * MLPH];

// ---------------- weight conversion ----------------
__global__ void cvt_all(const float* __restrict__ qw, const float* __restrict__ kvw,
                        const float* __restrict__ pw, const float* __restrict__ f1w,
                        const float* __restrict__ f2w) {
    int i = blockIdx.x * blockDim.x + threadIdx.x;
    if (i < Cc * Cc)     g_qw[i]  = __float2bfloat16(qw[i]);
    if (i < 2 * Cc * Cc) g_kvw[i] = __float2bfloat16(kvw[i]);
    if (i < Cc * Cc)     g_pw[i]  = __float2bfloat16(pw[i]);
    if (i < MLPH * Cc)   g_f1w[i] = __float2bfloat16(f1w[i]);
    if (i < Cc * MLPH)   g_f2w[i] = __float2bfloat16(f2w[i]);
}

// ---------------- LayerNorm helpers ----------------
__device__ __forceinline__ void block_reduce2(float& s, float& q, float* sS, float* sQ) {
    int lane = threadIdx.x & 31, wid = threadIdx.x >> 5;
#pragma unroll
    for (int o = 16; o; o >>= 1) {
        s += __shfl_xor_sync(0xffffffffu, s, o);
        q += __shfl_xor_sync(0xffffffffu, q, o);
    }
    if (lane == 0) { sS[wid] = s; sQ[wid] = q; }
    __syncthreads();
    s = sS[0] + sS[1] + sS[2] + sS[3];
    q = sQ[0] + sQ[1] + sQ[2] + sQ[3];
}

// LN of x and v, output bf16 in window-partitioned order
__global__ void ln1_kernel(const float* __restrict__ x, const float* __restrict__ v,
                           const float* __restrict__ g1, const float* __restrict__ b1,
                           const float* __restrict__ gv, const float* __restrict__ bv) {
    __shared__ float sS[4], sQ[4];
    int t = blockIdx.x;
    int c = threadIdx.x;
    // token -> window-token index
    int b = t / L, l = t - b * L;
    int row = l / Wdim, col = l - row * Wdim;
    int wy = row / WS, iy = row - wy * WS;
    int wx = col / WS, ix = col - wx * WS;
    int wt = ((b * WPB) + wy * 16 + wx) * NTOK + iy * WS + ix;

    {
        float xv = x[(size_t)t * Cc + c];
        float s = xv, q = xv * xv;
        block_reduce2(s, q, sS, sQ);
        float mu = s * (1.0f / Cc);
        float var = q * (1.0f / Cc) - mu * mu;
        float r = rsqrtf(var + EPS);
        g_xn[(size_t)wt * Cc + c] = __float2bfloat16((xv - mu) * r * g1[c] + b1[c]);
    }
    __syncthreads();
    {
        float xv = v[(size_t)t * Cc + c];
        float s = xv, q = xv * xv;
        block_reduce2(s, q, sS, sQ);
        float mu = s * (1.0f / Cc);
        float var = q * (1.0f / Cc) - mu * mu;
        float r = rsqrtf(var + EPS);
        g_vn[(size_t)wt * Cc + c] = __float2bfloat16((xv - mu) * r * gv[c] + bv[c]);
    }
}

// LN2: g_xo (fp32, token order) -> g_xon (bf16, token order)
__global__ void ln2_kernel(const float* __restrict__ g2, const float* __restrict__ b2) {
    __shared__ float sS[4], sQ[4];
    int t = blockIdx.x;
    int c = threadIdx.x;
    float xv = g_xo[(size_t)t * Cc + c];
    float s = xv, q = xv * xv;
    block_reduce2(s, q, sS, sQ);
    float mu = s * (1.0f / Cc);
    float var = q * (1.0f / Cc) - mu * mu;
    float r = rsqrtf(var + EPS);
    g_xon[(size_t)t * Cc + c] = __float2bfloat16((xv - mu) * r * g2[c] + b2[c]);
}

// ---------------- generic bf16 mma GEMM ----------------
// out[M,N] = A[M,K] @ W[N,K]^T  (row-major A, weights already [N][K])
// EPI: 0=Q  1=KV  2=PROJ(+x residual, scatter)  3=FC1(gelu)  4=FC2(+xo -> d_out)
template <int KD, int EPI>
__global__ void __launch_bounds__(256) gemm_bf16(const float* __restrict__ bias,
                                                 const float* __restrict__ res,
                                                 float* __restrict__ outf) {
    constexpr int BM = 128, BN = 64, BK = 32, LDSA = 40;
    __shared__ __nv_bfloat16 As[BM * LDSA];
    __shared__ __nv_bfloat16 Bs[BN * LDSA];

    const __nv_bfloat16* A =
        (EPI == 0) ? g_xn : (EPI == 1) ? g_vn : (EPI == 2) ? g_ao : (EPI == 3) ? g_xon : g_h1;
    const __nv_bfloat16* W =
        (EPI == 0) ? g_qw : (EPI == 1) ? g_kvw : (EPI == 2) ? g_pw : (EPI == 3) ? g_f1w : g_f2w;

    int tid = threadIdx.x;
    int m0 = blockIdx.x * BM, n0 = blockIdx.y * BN;
    int warp = tid >> 5, lane = tid & 31;
    int wm = (warp & 3) * 32;   // warp m-origin inside tile
    int wn = (warp >> 2) * 32;  // warp n-origin inside tile
    int g = lane >> 2, tg = lane & 3;

    float acc[2][4][4];
#pragma unroll
    for (int a = 0; a < 2; a++)
#pragma unroll
        for (int b = 0; b < 4; b++)
#pragma unroll
            for (int c = 0; c < 4; c++) acc[a][b][c] = 0.0f;

    for (int k0 = 0; k0 < KD; k0 += BK) {
        // load A tile: 128 rows x 32 cols, 512 uint4
#pragma unroll
        for (int vv = 0; vv < 2; vv++) {
            int idx = tid + vv * 256;
            int row = idx >> 2;
            int koff = (idx & 3) * 8;
            *(uint4*)(&As[row * LDSA + koff]) =
                *(const uint4*)(A + (size_t)(m0 + row) * KD + k0 + koff);
        }
        // load B tile: 64 rows x 32 cols, 256 uint4
        {
            int row = tid >> 2;
            int koff = (tid & 3) * 8;
            *(uint4*)(&Bs[row * LDSA + koff]) =
                *(const uint4*)(W + (size_t)(n0 + row) * KD + k0 + koff);
        }
        __syncthreads();
#pragma unroll
        for (int ks = 0; ks < BK; ks += 16) {
            uint32_t af[2][4], bf[4][2];
#pragma unroll
            for (int mi = 0; mi < 2; mi++) {
                int r0 = (wm + mi * 16 + g) * LDSA + ks + tg * 2;
                af[mi][0] = *(const uint32_t*)(&As[r0]);
                af[mi][1] = *(const uint32_t*)(&As[r0 + 8 * LDSA]);
                af[mi][2] = *(const uint32_t*)(&As[r0 + 8]);
                af[mi][3] = *(const uint32_t*)(&As[r0 + 8 * LDSA + 8]);
            }
#pragma unroll
            for (int ni = 0; ni < 4; ni++) {
                int r0 = (wn + ni * 8 + g) * LDSA + ks + tg * 2;
                bf[ni][0] = *(const uint32_t*)(&Bs[r0]);
                bf[ni][1] = *(const uint32_t*)(&Bs[r0 + 8]);
            }
#pragma unroll
            for (int mi = 0; mi < 2; mi++)
#pragma unroll
                for (int ni = 0; ni < 4; ni++) {
                    asm volatile(
                        "mma.sync.aligned.m16n8k16.row.col.f32.bf16.bf16.f32 "
                        "{%0,%1,%2,%3},{%4,%5,%6,%7},{%8,%9},{%0,%1,%2,%3};"
                        : "+f"(acc[mi][ni][0]), "+f"(acc[mi][ni][1]),
                          "+f"(acc[mi][ni][2]), "+f"(acc[mi][ni][3])
                        : "r"(af[mi][0]), "r"(af[mi][1]), "r"(af[mi][2]), "r"(af[mi][3]),
                          "r"(bf[ni][0]), "r"(bf[ni][1]));
                }
        }
        __syncthreads();
    }

    // ----- epilogue -----
#pragma unroll
    for (int mi = 0; mi < 2; mi++)
#pragma unroll
        for (int rr = 0; rr < 2; rr++) {
            int row = m0 + wm + mi * 16 + g + rr * 8;
            int trow = row;
            if (EPI == 2) {  // window-token row -> token index
                int win = row / NTOK, n = row - win * NTOK;
                int b = win >> 8, wr = win & 255;
                int wy = wr >> 4, wx = wr & 15;
                int iy = n / WS, ix = n - iy * WS;
                trow = b * L + (wy * WS + iy) * Wdim + wx * WS + ix;
            }
#pragma unroll
            for (int ni = 0; ni < 4; ni++)
#pragma unroll
                for (int cc = 0; cc < 2; cc++) {
                    int col = n0 + wn + ni * 8 + tg * 2 + cc;
                    float vacc = acc[mi][ni][rr * 2 + cc];
                    if (EPI == 0) {
                        g_q[(size_t)row * Cc + col] =
                            __float2bfloat16((vacc + bias[col]) * SCALE);
                    } else if (EPI == 1) {
                        float v2 = vacc + bias[col];
                        if (col < Cc)
                            g_k[(size_t)row * Cc + col] = __float2bfloat16(v2);
                        else
                            g_v[(size_t)row * Cc + (col - Cc)] = __float2bfloat16(v2);
                    } else if (EPI == 2) {
                        size_t oi = (size_t)trow * Cc + col;
                        g_xo[oi] = vacc + bias[col] + res[oi];
                    } else if (EPI == 3) {
                        float v2 = vacc + bias[col];
                        float ge = 0.5f * v2 * (1.0f + erff(v2 * 0.70710678118654752f));
                        g_h1[(size_t)row * MLPH + col] = __float2bfloat16(ge);
                    } else {
                        size_t oi = (size_t)row * Cc + col;
                        outf[oi] = vacc + bias[col] + g_xo[oi];
                    }
                }
        }
}

// ---------------- windowed attention (per window x head) ----------------
__global__ void __launch_bounds__(128) attn_kernel(const float* __restrict__ rpb) {
    __shared__ float sq[NTOK * HD], sk[NTOK * HD], sv[NTOK * HD];
    __shared__ float p[NTOK * NTOK];
    __shared__ float sb[169];

    int wh = blockIdx.x;
    int win = wh >> 2, head = wh & 3;
    int tid = threadIdx.x;
    size_t base = (size_t)(win * NTOK) * Cc + head * HD;

    for (int i = tid; i < NTOK * HD; i += 128) {
        int n = i >> 5, d = i & 31;
        sq[i] = __bfloat162float(g_q[base + (size_t)n * Cc + d]);
        sk[i] = __bfloat162float(g_k[base + (size_t)n * Cc + d]);
        sv[i] = __bfloat162float(g_v[base + (size_t)n * Cc + d]);
    }
    for (int i = tid; i < 169; i += 128) sb[i] = rpb[i * HEADS + head];
    __syncthreads();

    // logits + relative position bias
    for (int idx = tid; idx < NTOK * NTOK; idx += 128) {
        int n = idx / NTOK, m = idx - n * NTOK;
        const float* qn = &sq[n * HD];
        const float* km = &sk[m * HD];
        float a = 0.0f;
#pragma unroll
        for (int d = 0; d < HD; d++) a += qn[d] * km[d];
        int dy = n / WS - m / WS + (WS - 1);
        int dx = n % WS - m % WS + (WS - 1);
        p[idx] = a + sb[dy * (2 * WS - 1) + dx];
    }
    __syncthreads();

    // softmax per row (thread-per-row)
    if (tid < NTOK) {
        float mx = -1e30f;
        for (int m = 0; m < NTOK; m++) mx = fmaxf(mx, p[tid * NTOK + m]);
        float s = 0.0f;
        for (int m = 0; m < NTOK; m++) {
            float e = __expf(p[tid * NTOK + m] - mx);
            p[tid * NTOK + m] = e;
            s += e;
        }
        float inv = 1.0f / s;
        for (int m = 0; m < NTOK; m++) p[tid * NTOK + m] *= inv;
    }
    __syncthreads();

    // out = P @ V
    for (int idx = tid; idx < NTOK * HD; idx += 128) {
        int n = idx >> 5, d = idx & 31;
        float a = 0.0f;
#pragma unroll
        for (int m = 0; m < NTOK; m++) a += p[n * NTOK + m] * sv[m * HD + d];
        g_ao[base + (size_t)n * Cc + d] = __float2bfloat16(a);
    }
}

// ---------------- launch ----------------
extern "C" void kernel_launch(void* const* d_in, const int* in_sizes, int n_in,
                              void* d_out, int out_size) {
    const float* x   = (const float*)d_in[0];
    const float* v   = (const float*)d_in[1];
    const float* n1g = (const float*)d_in[2];
    const float* n1b = (const float*)d_in[3];
    const float* nvg = (const float*)d_in[4];
    const float* nvb = (const float*)d_in[5];
    const float* qw  = (const float*)d_in[6];
    const float* qb  = (const float*)d_in[7];
    const float* kvw = (const float*)d_in[8];
    const float* kvb = (const float*)d_in[9];
    const float* rpb = (const float*)d_in[10];
    const float* pw  = (const float*)d_in[11];
    const float* pb  = (const float*)d_in[12];
    const float* n2g = (const float*)d_in[13];
    const float* n2b = (const float*)d_in[14];
    const float* f1w = (const float*)d_in[15];
    const float* f1b = (const float*)d_in[16];
    const float* f2w = (const float*)d_in[17];
    const float* f2b = (const float*)d_in[18];
    float* out = (float*)d_out;

    cvt_all<<<(Cc * MLPH + 255) / 256, 256>>>(qw, kvw, pw, f1w, f2w);
    ln1_kernel<<<T, 128>>>(x, v, n1g, n1b, nvg, nvb);
    gemm_bf16<128, 0><<<dim3(T / 128, Cc / 64), 256>>>(qb, nullptr, nullptr);        // q
    gemm_bf16<128, 1><<<dim3(T / 128, 2 * Cc / 64), 256>>>(kvb, nullptr, nullptr);   // k,v
    attn_kernel<<<NWIN * HEADS, 128>>>(rpb);
    gemm_bf16<128, 2><<<dim3(T / 128, Cc / 64), 256>>>(pb, x, nullptr);              // proj + residual
    ln2_kernel<<<T, 128>>>(n2g, n2b);
    gemm_bf16<128, 3><<<dim3(T / 128, MLPH / 64), 256>>>(f1b, nullptr, nullptr);     // fc1 + gelu
    gemm_bf16<512, 4><<<dim3(T / 128, Cc / 64), 256>>>(f2b, nullptr, out);           // fc2 + residual
}

// round 2
// speedup vs baseline: 1.0907x; 1.0907x over previous
#include <cuda_runtime.h>
#include <cuda_bf16.h>
#include <cstdint>

// ---------------- problem constants ----------------
constexpr int Bsz   = 16;
constexpr int Hdim  = 112;
constexpr int Wdim  = 112;
constexpr int Cc    = 128;
constexpr int HEADS = 4;
constexpr int HD    = 32;
constexpr int WS    = 7;
constexpr int L     = Hdim * Wdim;        // 12544
constexpr int T     = Bsz * L;            // 200704
constexpr int NTOK  = WS * WS;            // 49
constexpr int WPB   = (Hdim / WS) * (Wdim / WS);  // 256
constexpr int NWIN  = Bsz * WPB;          // 4096
constexpr int MLPH  = 512;
constexpr float SCALE = 0.17677669529663687f;
constexpr float EPS   = 1e-5f;

// ---------------- device scratch ----------------
__device__ __align__(16) __nv_bfloat16 g_xn[T * Cc];
__device__ __align__(16) __nv_bfloat16 g_vn[T * Cc];
__device__ __align__(16) __nv_bfloat16 g_q [T * Cc];
__device__ __align__(16) __nv_bfloat16 g_k [T * Cc];
__device__ __align__(16) __nv_bfloat16 g_v [T * Cc];
__device__ __align__(16) __nv_bfloat16 g_ao[T * Cc];
__device__ __align__(16) float         g_xo[T * Cc];
__device__ __align__(16) __nv_bfloat16 g_xon[T * Cc];
__device__ __align__(16) __nv_bfloat16 g_h1[(size_t)T * MLPH];
__device__ __align__(16) __nv_bfloat16 g_qw [Cc * Cc];
__device__ __align__(16) __nv_bfloat16 g_kvw[2 * Cc * Cc];
__device__ __align__(16) __nv_bfloat16 g_pw [Cc * Cc];
__device__ __align__(16) __nv_bfloat16 g_f1w[MLPH * Cc];
__device__ __align__(16) __nv_bfloat16 g_f2w[Cc * MLPH];

// ---------------- helpers ----------------
__device__ __forceinline__ uint32_t s2u(const void* p) {
    return (uint32_t)__cvta_generic_to_shared(p);
}
__device__ __forceinline__ void ldsm4(uint32_t& r0, uint32_t& r1, uint32_t& r2,
                                      uint32_t& r3, uint32_t addr) {
    asm volatile("ldmatrix.sync.aligned.m8n8.x4.shared.b16 {%0,%1,%2,%3},[%4];"
                 : "=r"(r0), "=r"(r1), "=r"(r2), "=r"(r3) : "r"(addr));
}
__device__ __forceinline__ void cpasync16(uint32_t dst, const void* src) {
    asm volatile("cp.async.cg.shared.global [%0], [%1], 16;" :: "r"(dst), "l"(src));
}
__device__ __forceinline__ void cpcommit() { asm volatile("cp.async.commit_group;"); }
__device__ __forceinline__ void cpwait0()  { asm volatile("cp.async.wait_group 0;"); }

// ---------------- weight conversion ----------------
__global__ void cvt_all(const float* __restrict__ qw, const float* __restrict__ kvw,
                        const float* __restrict__ pw, const float* __restrict__ f1w,
                        const float* __restrict__ f2w) {
    int i = blockIdx.x * blockDim.x + threadIdx.x;
    if (i < Cc * Cc)     g_qw[i]  = __float2bfloat16(qw[i]);
    if (i < 2 * Cc * Cc) g_kvw[i] = __float2bfloat16(kvw[i]);
    if (i < Cc * Cc)     g_pw[i]  = __float2bfloat16(pw[i]);
    if (i < MLPH * Cc)   g_f1w[i] = __float2bfloat16(f1w[i]);
    if (i < Cc * MLPH)   g_f2w[i] = __float2bfloat16(f2w[i]);
}

// ---------------- warp-per-token LayerNorm ----------------
__device__ __forceinline__ void warp_red2(float& s, float& q) {
#pragma unroll
    for (int o = 16; o; o >>= 1) {
        s += __shfl_xor_sync(0xffffffffu, s, o);
        q += __shfl_xor_sync(0xffffffffu, q, o);
    }
}
__device__ __forceinline__ void ln_one(const float* __restrict__ src,
                                       const float* __restrict__ gamma,
                                       const float* __restrict__ beta,
                                       __nv_bfloat16* __restrict__ dst,
                                       int t, int wt, int lane) {
    float4 xv = ((const float4*)(src + (size_t)t * Cc))[lane];
    float s = xv.x + xv.y + xv.z + xv.w;
    float q = xv.x * xv.x + xv.y * xv.y + xv.z * xv.z + xv.w * xv.w;
    warp_red2(s, q);
    float mu = s * (1.0f / Cc);
    float var = q * (1.0f / Cc) - mu * mu;
    float r = rsqrtf(var + EPS);
    float4 g = ((const float4*)gamma)[lane];
    float4 b = ((const float4*)beta)[lane];
    __nv_bfloat162 p0 = {__float2bfloat16((xv.x - mu) * r * g.x + b.x),
                         __float2bfloat16((xv.y - mu) * r * g.y + b.y)};
    __nv_bfloat162 p1 = {__float2bfloat16((xv.z - mu) * r * g.z + b.z),
                         __float2bfloat16((xv.w - mu) * r * g.w + b.w)};
    uint2 out;
    out.x = *(uint32_t*)&p0;
    out.y = *(uint32_t*)&p1;
    *(uint2*)(dst + (size_t)wt * Cc + lane * 4) = out;
}

__global__ void __launch_bounds__(256) ln1_kernel(
    const float* __restrict__ x, const float* __restrict__ v,
    const float* __restrict__ g1, const float* __restrict__ b1,
    const float* __restrict__ gv, const float* __restrict__ bv) {
    int warp = threadIdx.x >> 5, lane = threadIdx.x & 31;
    int t = blockIdx.x * 8 + warp;
    int b = t / L, l = t - b * L;
    int row = l / Wdim, col = l - row * Wdim;
    int wy = row / WS, iy = row - wy * WS;
    int wx = col / WS, ix = col - wx * WS;
    int wt = ((b * WPB) + wy * 16 + wx) * NTOK + iy * WS + ix;
    ln_one(x, g1, b1, g_xn, t, wt, lane);
    ln_one(v, gv, bv, g_vn, t, wt, lane);
}

__global__ void __launch_bounds__(256) ln2_kernel(
    const float* __restrict__ g2, const float* __restrict__ b2) {
    int warp = threadIdx.x >> 5, lane = threadIdx.x & 31;
    int t = blockIdx.x * 8 + warp;
    ln_one(g_xo, g2, b2, g_xon, t, t, lane);
}

// ---------------- pipelined bf16 tensor-core GEMM ----------------
// out[M,N] = A[M,K] @ W[N,K]^T
// EPI: 0=Q  1=KV  2=PROJ(+x, scatter)  3=FC1(gelu)  4=FC2(+xo -> d_out)
template <int KD, int EPI>
__global__ void __launch_bounds__(256) gemm_bf16(const float* __restrict__ bias,
                                                 const float* __restrict__ res,
                                                 float* __restrict__ outf) {
    constexpr int BM = 128, BN = 128, BK = 32, LDS = 40;  // 80B row stride
    __shared__ __nv_bfloat16 As[2][BM * LDS];
    __shared__ __nv_bfloat16 Bs[2][BN * LDS];

    const __nv_bfloat16* A =
        (EPI == 0) ? g_xn : (EPI == 1) ? g_vn : (EPI == 2) ? g_ao : (EPI == 3) ? g_xon : g_h1;
    const __nv_bfloat16* W =
        (EPI == 0) ? g_qw : (EPI == 1) ? g_kvw : (EPI == 2) ? g_pw : (EPI == 3) ? g_f1w : g_f2w;

    const int tid = threadIdx.x;
    const int m0 = blockIdx.x * BM, n0 = blockIdx.y * BN;
    const int warp = tid >> 5, lane = tid & 31;
    const int wm = (warp & 3) * 32;   // 4 warps over M
    const int wn = (warp >> 2) * 64;  // 2 warps over N
    const int g = lane >> 2, tg = lane & 3;

    // cp.async source/dest indices: thread handles chunks tid and tid+256 of 512
    const int ar0 = tid >> 2, ac0 = (tid & 3) * 8;
    const int ar1 = (tid + 256) >> 2, ac1 = ((tid + 256) & 3) * 8;

    float acc[2][8][4];
#pragma unroll
    for (int a = 0; a < 2; a++)
#pragma unroll
        for (int b = 0; b < 8; b++)
#pragma unroll
            for (int c = 0; c < 4; c++) acc[a][b][c] = 0.0f;

    auto load_tiles = [&](int buf, int k0) {
        cpasync16(s2u(&As[buf][ar0 * LDS + ac0]), A + (size_t)(m0 + ar0) * KD + k0 + ac0);
        cpasync16(s2u(&As[buf][ar1 * LDS + ac1]), A + (size_t)(m0 + ar1) * KD + k0 + ac1);
        cpasync16(s2u(&Bs[buf][ar0 * LDS + ac0]), W + (size_t)(n0 + ar0) * KD + k0 + ac0);
        cpasync16(s2u(&Bs[buf][ar1 * LDS + ac1]), W + (size_t)(n0 + ar1) * KD + k0 + ac1);
    };

    // ldmatrix base addresses (per-lane)
    const int a_row = wm + (lane & 15);
    const int a_cb  = (lane >> 4) * 8;
    const int b_row = wn + ((lane >> 4) << 3) + (lane & 7);
    const int b_cb  = ((lane >> 3) & 1) * 8;

    constexpr int NK = KD / BK;
    load_tiles(0, 0);
    cpcommit();

    for (int kt = 0; kt < NK; kt++) {
        cpwait0();
        __syncthreads();
        if (kt + 1 < NK) {
            load_tiles((kt + 1) & 1, (kt + 1) * BK);
            cpcommit();
        }
        const int buf = kt & 1;
#pragma unroll
        for (int kh = 0; kh < 2; kh++) {
            uint32_t a[2][4];
#pragma unroll
            for (int mi = 0; mi < 2; mi++) {
                uint32_t addr = s2u(&As[buf][(a_row + mi * 16) * LDS + kh * 16 + a_cb]);
                ldsm4(a[mi][0], a[mi][1], a[mi][2], a[mi][3], addr);
            }
            uint32_t b[4][4];
#pragma unroll
            for (int nj = 0; nj < 4; nj++) {
                uint32_t addr = s2u(&Bs[buf][(b_row + nj * 16) * LDS + kh * 16 + b_cb]);
                ldsm4(b[nj][0], b[nj][1], b[nj][2], b[nj][3], addr);
            }
#pragma unroll
            for (int mi = 0; mi < 2; mi++)
#pragma unroll
                for (int ni = 0; ni < 8; ni++) {
                    const uint32_t b0 = b[ni >> 1][(ni & 1) * 2];
                    const uint32_t b1 = b[ni >> 1][(ni & 1) * 2 + 1];
                    asm volatile(
                        "mma.sync.aligned.m16n8k16.row.col.f32.bf16.bf16.f32 "
                        "{%0,%1,%2,%3},{%4,%5,%6,%7},{%8,%9},{%0,%1,%2,%3};"
                        : "+f"(acc[mi][ni][0]), "+f"(acc[mi][ni][1]),
                          "+f"(acc[mi][ni][2]), "+f"(acc[mi][ni][3])
                        : "r"(a[mi][0]), "r"(a[mi][1]), "r"(a[mi][2]), "r"(a[mi][3]),
                          "r"(b0), "r"(b1));
                }
        }
        __syncthreads();
    }

    // ----- epilogue -----
#pragma unroll
    for (int mi = 0; mi < 2; mi++)
#pragma unroll
        for (int rr = 0; rr < 2; rr++) {
            int row = m0 + wm + mi * 16 + g + rr * 8;
            int trow = row;
            if (EPI == 2) {
                int win = row / NTOK, n = row - win * NTOK;
                int b = win >> 8, wr = win & 255;
                int wy = wr >> 4, wx = wr & 15;
                int iy = n / WS, ix = n - iy * WS;
                trow = b * L + (wy * WS + iy) * Wdim + wx * WS + ix;
            }
#pragma unroll
            for (int ni = 0; ni < 8; ni++)
#pragma unroll
                for (int cc = 0; cc < 2; cc++) {
                    int col = n0 + wn + ni * 8 + tg * 2 + cc;
                    float vacc = acc[mi][ni][rr * 2 + cc];
                    if (EPI == 0) {
                        g_q[(size_t)row * Cc + col] =
                            __float2bfloat16((vacc + bias[col]) * SCALE);
                    } else if (EPI == 1) {
                        float v2 = vacc + bias[col];
                        if (col < Cc)
                            g_k[(size_t)row * Cc + col] = __float2bfloat16(v2);
                        else
                            g_v[(size_t)row * Cc + (col - Cc)] = __float2bfloat16(v2);
                    } else if (EPI == 2) {
                        size_t oi = (size_t)trow * Cc + col;
                        g_xo[oi] = vacc + bias[col] + res[oi];
                    } else if (EPI == 3) {
                        float v2 = vacc + bias[col];
                        float ge = 0.5f * v2 * (1.0f + erff(v2 * 0.70710678118654752f));
                        g_h1[(size_t)row * MLPH + col] = __float2bfloat16(ge);
                    } else {
                        size_t oi = (size_t)row * Cc + col;
                        outf[oi] = vacc + bias[col] + g_xo[oi];
                    }
                }
        }
}

// ---------------- windowed attention (per window x head) ----------------
__global__ void __launch_bounds__(128) attn_kernel(const float* __restrict__ rpb) {
    __shared__ float sq[NTOK * HD], sk[NTOK * HD], sv[NTOK * HD];
    __shared__ float p[NTOK * NTOK];
    __shared__ float sb[169];

    int wh = blockIdx.x;
    int win = wh >> 2, head = wh & 3;
    int tid = threadIdx.x;
    size_t base = (size_t)(win * NTOK) * Cc + head * HD;

    for (int i = tid; i < NTOK * HD; i += 128) {
        int n = i >> 5, d = i & 31;
        sq[i] = __bfloat162float(g_q[base + (size_t)n * Cc + d]);
        sk[i] = __bfloat162float(g_k[base + (size_t)n * Cc + d]);
        sv[i] = __bfloat162float(g_v[base + (size_t)n * Cc + d]);
    }
    for (int i = tid; i < 169; i += 128) sb[i] = rpb[i * HEADS + head];
    __syncthreads();

    for (int idx = tid; idx < NTOK * NTOK; idx += 128) {
        int n = idx / NTOK, m = idx - n * NTOK;
        const float* qn = &sq[n * HD];
        const float* km = &sk[m * HD];
        float a = 0.0f;
#pragma unroll
        for (int d = 0; d < HD; d++) a += qn[d] * km[d];
        int dy = n / WS - m / WS + (WS - 1);
        int dx = n % WS - m % WS + (WS - 1);
        p[idx] = a + sb[dy * (2 * WS - 1) + dx];
    }
    __syncthreads();

    if (tid < NTOK) {
        float mx = -1e30f;
        for (int m = 0; m < NTOK; m++) mx = fmaxf(mx, p[tid * NTOK + m]);
        float s = 0.0f;
        for (int m = 0; m < NTOK; m++) {
            float e = __expf(p[tid * NTOK + m] - mx);
            p[tid * NTOK + m] = e;
            s += e;
        }
        float inv = 1.0f / s;
        for (int m = 0; m < NTOK; m++) p[tid * NTOK + m] *= inv;
    }
    __syncthreads();

    for (int idx = tid; idx < NTOK * HD; idx += 128) {
        int n = idx >> 5, d = idx & 31;
        float a = 0.0f;
#pragma unroll
        for (int m = 0; m < NTOK; m++) a += p[n * NTOK + m] * sv[m * HD + d];
        g_ao[base + (size_t)n * Cc + d] = __float2bfloat16(a);
    }
}

// ---------------- launch ----------------
extern "C" void kernel_launch(void* const* d_in, const int* in_sizes, int n_in,
                              void* d_out, int out_size) {
    const float* x   = (const float*)d_in[0];
    const float* v   = (const float*)d_in[1];
    const float* n1g = (const float*)d_in[2];
    const float* n1b = (const float*)d_in[3];
    const float* nvg = (const float*)d_in[4];
    const float* nvb = (const float*)d_in[5];
    const float* qw  = (const float*)d_in[6];
    const float* qb  = (const float*)d_in[7];
    const float* kvw = (const float*)d_in[8];
    const float* kvb = (const float*)d_in[9];
    const float* rpb = (const float*)d_in[10];
    const float* pw  = (const float*)d_in[11];
    const float* pb  = (const float*)d_in[12];
    const float* n2g = (const float*)d_in[13];
    const float* n2b = (const float*)d_in[14];
    const float* f1w = (const float*)d_in[15];
    const float* f1b = (const float*)d_in[16];
    const float* f2w = (const float*)d_in[17];
    const float* f2b = (const float*)d_in[18];
    float* out = (float*)d_out;

    cvt_all<<<(Cc * MLPH + 255) / 256, 256>>>(qw, kvw, pw, f1w, f2w);
    ln1_kernel<<<T / 8, 256>>>(x, v, n1g, n1b, nvg, nvb);
    gemm_bf16<128, 0><<<dim3(T / 128, 1), 256>>>(qb, nullptr, nullptr);       // q
    gemm_bf16<128, 1><<<dim3(T / 128, 2), 256>>>(kvb, nullptr, nullptr);      // k,v
    attn_kernel<<<NWIN * HEADS, 128>>>(rpb);
    gemm_bf16<128, 2><<<dim3(T / 128, 1), 256>>>(pb, x, nullptr);             // proj + residual
    ln2_kernel<<<T / 8, 256>>>(n2g, n2b);
    gemm_bf16<128, 3><<<dim3(T / 128, 4), 256>>>(f1b, nullptr, nullptr);      // fc1 + gelu
    gemm_bf16<512, 4><<<dim3(T / 128, 1), 256>>>(f2b, nullptr, out);          // fc2 + residual
}

// round 3
// speedup vs baseline: 2.6222x; 2.4042x over previous
#include <cuda_runtime.h>
#include <cuda_bf16.h>
#include <cstdint>

// ---------------- problem constants ----------------
constexpr int Bsz   = 16;
constexpr int Hdim  = 112;
constexpr int Wdim  = 112;
constexpr int Cc    = 128;
constexpr int HEADS = 4;
constexpr int HD    = 32;
constexpr int WS    = 7;
constexpr int L     = Hdim * Wdim;        // 12544
constexpr int T     = Bsz * L;            // 200704
constexpr int NTOK  = WS * WS;            // 49
constexpr int WPB   = (Hdim / WS) * (Wdim / WS);  // 256
constexpr int NWIN  = Bsz * WPB;          // 4096
constexpr int MLPH  = 512;
constexpr float SCALE = 0.17677669529663687f;
constexpr float EPS   = 1e-5f;

// ---------------- device scratch ----------------
__device__ __align__(16) __nv_bfloat16 g_xn[T * Cc];
__device__ __align__(16) __nv_bfloat16 g_vn[T * Cc];
__device__ __align__(16) __nv_bfloat16 g_q [T * Cc];
__device__ __align__(16) __nv_bfloat16 g_k [T * Cc];
__device__ __align__(16) __nv_bfloat16 g_v [T * Cc];
__device__ __align__(16) __nv_bfloat16 g_ao[T * Cc];
__device__ __align__(16) float         g_xo[T * Cc];
__device__ __align__(16) __nv_bfloat16 g_xon[T * Cc];
__device__ __align__(16) __nv_bfloat16 g_h1[(size_t)T * MLPH];
__device__ __align__(16) __nv_bfloat16 g_qw [Cc * Cc];
__device__ __align__(16) __nv_bfloat16 g_kvw[2 * Cc * Cc];
__device__ __align__(16) __nv_bfloat16 g_pw [Cc * Cc];
__device__ __align__(16) __nv_bfloat16 g_f1w[MLPH * Cc];
__device__ __align__(16) __nv_bfloat16 g_f2w[Cc * MLPH];

// ---------------- helpers ----------------
__device__ __forceinline__ uint32_t s2u(const void* p) {
    return (uint32_t)__cvta_generic_to_shared(p);
}
__device__ __forceinline__ void ldsm4(uint32_t& r0, uint32_t& r1, uint32_t& r2,
                                      uint32_t& r3, uint32_t addr) {
    asm volatile("ldmatrix.sync.aligned.m8n8.x4.shared.b16 {%0,%1,%2,%3},[%4];"
                 : "=r"(r0), "=r"(r1), "=r"(r2), "=r"(r3) : "r"(addr));
}
__device__ __forceinline__ void cpasync16(uint32_t dst, const void* src) {
    asm volatile("cp.async.cg.shared.global [%0], [%1], 16;" :: "r"(dst), "l"(src));
}
__device__ __forceinline__ void cpcommit() { asm volatile("cp.async.commit_group;"); }
__device__ __forceinline__ void cpwait0()  { asm volatile("cp.async.wait_group 0;"); }

__device__ __forceinline__ void mma16816(float* c, const uint32_t* a, const uint32_t* b) {
    asm volatile(
        "mma.sync.aligned.m16n8k16.row.col.f32.bf16.bf16.f32 "
        "{%0,%1,%2,%3},{%4,%5,%6,%7},{%8,%9},{%0,%1,%2,%3};"
        : "+f"(c[0]), "+f"(c[1]), "+f"(c[2]), "+f"(c[3])
        : "r"(a[0]), "r"(a[1]), "r"(a[2]), "r"(a[3]), "r"(b[0]), "r"(b[1]));
}

// ---------------- weight conversion ----------------
__global__ void cvt_all(const float* __restrict__ qw, const float* __restrict__ kvw,
                        const float* __restrict__ pw, const float* __restrict__ f1w,
                        const float* __restrict__ f2w) {
    int i = blockIdx.x * blockDim.x + threadIdx.x;
    if (i < Cc * Cc)     g_qw[i]  = __float2bfloat16(qw[i]);
    if (i < 2 * Cc * Cc) g_kvw[i] = __float2bfloat16(kvw[i]);
    if (i < Cc * Cc)     g_pw[i]  = __float2bfloat16(pw[i]);
    if (i < MLPH * Cc)   g_f1w[i] = __float2bfloat16(f1w[i]);
    if (i < Cc * MLPH)   g_f2w[i] = __float2bfloat16(f2w[i]);
}

// ---------------- warp-per-token LayerNorm ----------------
__device__ __forceinline__ void warp_red2(float& s, float& q) {
#pragma unroll
    for (int o = 16; o; o >>= 1) {
        s += __shfl_xor_sync(0xffffffffu, s, o);
        q += __shfl_xor_sync(0xffffffffu, q, o);
    }
}
__device__ __forceinline__ void ln_one(const float* __restrict__ src,
                                       const float* __restrict__ gamma,
                                       const float* __restrict__ beta,
                                       __nv_bfloat16* __restrict__ dst,
                                       int t, int wt, int lane) {
    float4 xv = ((const float4*)(src + (size_t)t * Cc))[lane];
    float s = xv.x + xv.y + xv.z + xv.w;
    float q = xv.x * xv.x + xv.y * xv.y + xv.z * xv.z + xv.w * xv.w;
    warp_red2(s, q);
    float mu = s * (1.0f / Cc);
    float var = q * (1.0f / Cc) - mu * mu;
    float r = rsqrtf(var + EPS);
    float4 g = ((const float4*)gamma)[lane];
    float4 b = ((const float4*)beta)[lane];
    __nv_bfloat162 p0 = {__float2bfloat16((xv.x - mu) * r * g.x + b.x),
                         __float2bfloat16((xv.y - mu) * r * g.y + b.y)};
    __nv_bfloat162 p1 = {__float2bfloat16((xv.z - mu) * r * g.z + b.z),
                         __float2bfloat16((xv.w - mu) * r * g.w + b.w)};
    uint2 out;
    out.x = *(uint32_t*)&p0;
    out.y = *(uint32_t*)&p1;
    *(uint2*)(dst + (size_t)wt * Cc + lane * 4) = out;
}

__global__ void __launch_bounds__(256) ln1_kernel(
    const float* __restrict__ x, const float* __restrict__ v,
    const float* __restrict__ g1, const float* __restrict__ b1,
    const float* __restrict__ gv, const float* __restrict__ bv) {
    int warp = threadIdx.x >> 5, lane = threadIdx.x & 31;
    int t = blockIdx.x * 8 + warp;
    int b = t / L, l = t - b * L;
    int row = l / Wdim, col = l - row * Wdim;
    int wy = row / WS, iy = row - wy * WS;
    int wx = col / WS, ix = col - wx * WS;
    int wt = ((b * WPB) + wy * 16 + wx) * NTOK + iy * WS + ix;
    ln_one(x, g1, b1, g_xn, t, wt, lane);
    ln_one(v, gv, bv, g_vn, t, wt, lane);
}

__global__ void __launch_bounds__(256) ln2_kernel(
    const float* __restrict__ g2, const float* __restrict__ b2) {
    int warp = threadIdx.x >> 5, lane = threadIdx.x & 31;
    int t = blockIdx.x * 8 + warp;
    ln_one(g_xo, g2, b2, g_xon, t, t, lane);
}

// ---------------- pipelined bf16 tensor-core GEMM (128x64 tile) ----------------
// out[M,N] = A[M,K] @ W[N,K]^T
// EPI: 0=Q  1=KV  2=PROJ(+x, scatter)  3=FC1(gelu)  4=FC2(+xo -> d_out)
template <int KD, int EPI>
__global__ void __launch_bounds__(256) gemm_bf16(const float* __restrict__ bias,
                                                 const float* __restrict__ res,
                                                 float* __restrict__ outf) {
    constexpr int BM = 128, BN = 64, BK = 32, LDS = 40;
    __shared__ __nv_bfloat16 As[2][BM * LDS];
    __shared__ __nv_bfloat16 Bs[2][BN * LDS];

    const __nv_bfloat16* A =
        (EPI == 0) ? g_xn : (EPI == 1) ? g_vn : (EPI == 2) ? g_ao : (EPI == 3) ? g_xon : g_h1;
    const __nv_bfloat16* W =
        (EPI == 0) ? g_qw : (EPI == 1) ? g_kvw : (EPI == 2) ? g_pw : (EPI == 3) ? g_f1w : g_f2w;

    const int tid = threadIdx.x;
    const int m0 = blockIdx.x * BM, n0 = blockIdx.y * BN;
    const int warp = tid >> 5, lane = tid & 31;
    const int wm = (warp & 3) * 32;   // 4 warps over M
    const int wn = (warp >> 2) * 32;  // 2 warps over N
    const int g = lane >> 2, tg = lane & 3;

    const int ar0 = tid >> 2, ac0 = (tid & 3) * 8;
    const int ar1 = (tid + 256) >> 2, ac1 = ((tid + 256) & 3) * 8;

    float acc[2][4][4];
#pragma unroll
    for (int a = 0; a < 2; a++)
#pragma unroll
        for (int b = 0; b < 4; b++)
#pragma unroll
            for (int c = 0; c < 4; c++) acc[a][b][c] = 0.0f;

    auto load_tiles = [&](int buf, int k0) {
        cpasync16(s2u(&As[buf][ar0 * LDS + ac0]), A + (size_t)(m0 + ar0) * KD + k0 + ac0);
        cpasync16(s2u(&As[buf][ar1 * LDS + ac1]), A + (size_t)(m0 + ar1) * KD + k0 + ac1);
        cpasync16(s2u(&Bs[buf][ar0 * LDS + ac0]), W + (size_t)(n0 + ar0) * KD + k0 + ac0);
    };

    const int a_row = wm + (lane & 15);
    const int a_cb  = (lane >> 4) * 8;
    const int b_row = wn + ((lane >> 4) << 3) + (lane & 7);
    const int b_cb  = ((lane >> 3) & 1) * 8;

    constexpr int NK = KD / BK;
    load_tiles(0, 0);
    cpcommit();

    for (int kt = 0; kt < NK; kt++) {
        cpwait0();
        __syncthreads();
        if (kt + 1 < NK) {
            load_tiles((kt + 1) & 1, (kt + 1) * BK);
            cpcommit();
        }
        const int buf = kt & 1;
#pragma unroll
        for (int kh = 0; kh < 2; kh++) {
            uint32_t a[2][4];
#pragma unroll
            for (int mi = 0; mi < 2; mi++) {
                uint32_t addr = s2u(&As[buf][(a_row + mi * 16) * LDS + kh * 16 + a_cb]);
                ldsm4(a[mi][0], a[mi][1], a[mi][2], a[mi][3], addr);
            }
            uint32_t b[2][4];
#pragma unroll
            for (int nj = 0; nj < 2; nj++) {
                uint32_t addr = s2u(&Bs[buf][(b_row + nj * 16) * LDS + kh * 16 + b_cb]);
                ldsm4(b[nj][0], b[nj][1], b[nj][2], b[nj][3], addr);
            }
#pragma unroll
            for (int mi = 0; mi < 2; mi++)
#pragma unroll
                for (int ni = 0; ni < 4; ni++) {
                    uint32_t bb[2] = {b[ni >> 1][(ni & 1) * 2], b[ni >> 1][(ni & 1) * 2 + 1]};
                    mma16816(acc[mi][ni], a[mi], bb);
                }
        }
        __syncthreads();
    }

    // ----- epilogue -----
#pragma unroll
    for (int mi = 0; mi < 2; mi++)
#pragma unroll
        for (int rr = 0; rr < 2; rr++) {
            int row = m0 + wm + mi * 16 + g + rr * 8;
            int trow = row;
            if (EPI == 2) {
                int win = row / NTOK, n = row - win * NTOK;
                int b = win >> 8, wr = win & 255;
                int wy = wr >> 4, wx = wr & 15;
                int iy = n / WS, ix = n - iy * WS;
                trow = b * L + (wy * WS + iy) * Wdim + wx * WS + ix;
            }
#pragma unroll
            for (int ni = 0; ni < 4; ni++)
#pragma unroll
                for (int cc = 0; cc < 2; cc++) {
                    int col = n0 + wn + ni * 8 + tg * 2 + cc;
                    float vacc = acc[mi][ni][rr * 2 + cc];
                    if (EPI == 0) {
                        g_q[(size_t)row * Cc + col] =
                            __float2bfloat16((vacc + bias[col]) * SCALE);
                    } else if (EPI == 1) {
                        float v2 = vacc + bias[col];
                        if (col < Cc)
                            g_k[(size_t)row * Cc + col] = __float2bfloat16(v2);
                        else
                            g_v[(size_t)row * Cc + (col - Cc)] = __float2bfloat16(v2);
                    } else if (EPI == 2) {
                        size_t oi = (size_t)trow * Cc + col;
                        g_xo[oi] = vacc + bias[col] + res[oi];
                    } else if (EPI == 3) {
                        float v2 = vacc + bias[col];
                        float ge = 0.5f * v2 * (1.0f + erff(v2 * 0.70710678118654752f));
                        g_h1[(size_t)row * MLPH + col] = __float2bfloat16(ge);
                    } else {
                        size_t oi = (size_t)row * Cc + col;
                        outf[oi] = vacc + bias[col] + g_xo[oi];
                    }
                }
        }
}

// ---------------- tensor-core windowed attention ----------------
// one block per window, one warp per head
__global__ void __launch_bounds__(128) attn_kernel(const float* __restrict__ rpb) {
    constexpr int SST = 136;
    __shared__ __nv_bfloat16 sK[64 * SST];
    __shared__ __nv_bfloat16 sV[64 * SST];
    __shared__ float sb[HEADS * 169];

    const int win = blockIdx.x;
    const int tid = threadIdx.x, warp = tid >> 5, lane = tid & 31;
    const int g = lane >> 2, tg = lane & 3;
    const size_t base = (size_t)win * NTOK * Cc;

    for (int i = tid; i < 49 * 16; i += 128) {
        int r = i >> 4, cb = (i & 15) * 8;
        *(uint4*)&sK[r * SST + cb] = *(const uint4*)(g_k + base + (size_t)r * Cc + cb);
        *(uint4*)&sV[r * SST + cb] = *(const uint4*)(g_v + base + (size_t)r * Cc + cb);
    }
    for (int i = tid; i < 15 * 16; i += 128) {  // zero V pad rows (NaN safety)
        int r = 49 + (i >> 4), cb = (i & 15) * 8;
        *(uint4*)&sV[r * SST + cb] = make_uint4(0, 0, 0, 0);
    }
    for (int i = lane; i < 169; i += 32) sb[warp * 169 + i] = rpb[i * HEADS + warp];
    __syncthreads();

    const int hc = warp * HD;
    const float* sbh = &sb[warp * 169];

    // K b-frags (persistent): kb[nt][kh] = K[key=nt*8+g][d = kh*16 + tg*2 (+1), +8]
    uint32_t kb[7][2][2];
#pragma unroll
    for (int nt = 0; nt < 7; nt++)
#pragma unroll
        for (int kh = 0; kh < 2; kh++) {
            const __nv_bfloat16* p = &sK[(nt * 8 + g) * SST + hc + kh * 16 + tg * 2];
            kb[nt][kh][0] = *(const uint32_t*)p;
            kb[nt][kh][1] = *(const uint32_t*)(p + 8);
        }
    // V b-frags (persistent): vb[kt][nd]: B[n=dim][k=key], keys kt*16.., dims nd*8..
    uint32_t vb[4][4][2];
#pragma unroll
    for (int kt = 0; kt < 4; kt++)
#pragma unroll
        for (int nd = 0; nd < 4; nd++) {
            int k0 = kt * 16 + tg * 2;
            int c = hc + nd * 8 + g;
            __nv_bfloat162 b0 = {sV[k0 * SST + c], sV[(k0 + 1) * SST + c]};
            __nv_bfloat162 b1 = {sV[(k0 + 8) * SST + c], sV[(k0 + 9) * SST + c]};
            vb[kt][nd][0] = *(uint32_t*)&b0;
            vb[kt][nd][1] = *(uint32_t*)&b1;
        }

#pragma unroll
    for (int mt = 0; mt < 4; mt++) {
        // Q a-frags straight from global (g_q pre-scaled)
        uint32_t qa[2][4];
        int q0 = win * NTOK + mt * 16 + g;
        int q1 = q0 + 8;
        int q0c = q0 < T ? q0 : T - 1;
        int q1c = q1 < T ? q1 : T - 1;
#pragma unroll
        for (int kh = 0; kh < 2; kh++) {
            const __nv_bfloat16* p0 = g_q + (size_t)q0c * Cc + hc + kh * 16 + tg * 2;
            const __nv_bfloat16* p1 = g_q + (size_t)q1c * Cc + hc + kh * 16 + tg * 2;
            qa[kh][0] = *(const uint32_t*)p0;
            qa[kh][1] = *(const uint32_t*)p1;
            qa[kh][2] = *(const uint32_t*)(p0 + 8);
            qa[kh][3] = *(const uint32_t*)(p1 + 8);
        }

        float s[7][4];
#pragma unroll
        for (int nt = 0; nt < 7; nt++)
#pragma unroll
            for (int c = 0; c < 4; c++) s[nt][c] = 0.0f;
#pragma unroll
        for (int kh = 0; kh < 2; kh++)
#pragma unroll
            for (int nt = 0; nt < 7; nt++) mma16816(s[nt], qa[kh], kb[nt][kh]);

        // softmax (rows live in lane quads) + pack P into a-frags
        uint32_t pa[4][4];
#pragma unroll
        for (int rr = 0; rr < 2; rr++) {
            int q = mt * 16 + g + rr * 8;
            int qq = q < NTOK ? q : NTOK - 1;
            int qy = qq / WS, qx = qq - qy * WS;
            float ev[14];
            float mx = -1e30f;
#pragma unroll
            for (int nt = 0; nt < 7; nt++)
#pragma unroll
                for (int cc = 0; cc < 2; cc++) {
                    int key = nt * 8 + tg * 2 + cc;
                    float v = s[nt][rr * 2 + cc];
                    if (key < NTOK) {
                        int ky = key / WS, kx = key - ky * WS;
                        v += sbh[(qy - ky + 6) * 13 + (qx - kx + 6)];
                        mx = fmaxf(mx, v);
                    }
                    ev[nt * 2 + cc] = v;
                }
            mx = fmaxf(mx, __shfl_xor_sync(0xffffffffu, mx, 1));
            mx = fmaxf(mx, __shfl_xor_sync(0xffffffffu, mx, 2));
            float sum = 0.0f;
#pragma unroll
            for (int j = 0; j < 14; j++) {
                int key = (j >> 1) * 8 + tg * 2 + (j & 1);
                float e = (key < NTOK) ? __expf(ev[j] - mx) : 0.0f;
                ev[j] = e;
                sum += e;
            }
            sum += __shfl_xor_sync(0xffffffffu, sum, 1);
            sum += __shfl_xor_sync(0xffffffffu, sum, 2);
            float inv = 1.0f / sum;
#pragma unroll
            for (int kt = 0; kt < 4; kt++) {
                int ntA = 2 * kt, ntB = 2 * kt + 1;
                __nv_bfloat162 pA = __float22bfloat162_rn(
                    make_float2(ev[ntA * 2] * inv, ev[ntA * 2 + 1] * inv));
                pa[kt][rr] = *(uint32_t*)&pA;
                if (ntB < 7) {
                    __nv_bfloat162 pB = __float22bfloat162_rn(
                        make_float2(ev[ntB * 2] * inv, ev[ntB * 2 + 1] * inv));
                    pa[kt][2 + rr] = *(uint32_t*)&pB;
                } else {
                    pa[kt][2 + rr] = 0u;
                }
            }
        }

        // out = P @ V
        float o[4][4];
#pragma unroll
        for (int nd = 0; nd < 4; nd++)
#pragma unroll
            for (int c = 0; c < 4; c++) o[nd][c] = 0.0f;
#pragma unroll
        for (int kt = 0; kt < 4; kt++)
#pragma unroll
            for (int nd = 0; nd < 4; nd++) mma16816(o[nd], pa[kt], vb[kt][nd]);

#pragma unroll
        for (int rr = 0; rr < 2; rr++) {
            int q = mt * 16 + g + rr * 8;
            if (q < NTOK) {
#pragma unroll
                for (int nd = 0; nd < 4; nd++) {
                    __nv_bfloat162 p2 = __float22bfloat162_rn(
                        make_float2(o[nd][rr * 2], o[nd][rr * 2 + 1]));
                    *(uint32_t*)(g_ao + base + (size_t)q * Cc + hc + nd * 8 + tg * 2) =
                        *(uint32_t*)&p2;
                }
            }
        }
    }
}

// ---------------- launch ----------------
extern "C" void kernel_launch(void* const* d_in, const int* in_sizes, int n_in,
                              void* d_out, int out_size) {
    const float* x   = (const float*)d_in[0];
    const float* v   = (const float*)d_in[1];
    const float* n1g = (const float*)d_in[2];
    const float* n1b = (const float*)d_in[3];
    const float* nvg = (const float*)d_in[4];
    const float* nvb = (const float*)d_in[5];
    const float* qw  = (const float*)d_in[6];
    const float* qb  = (const float*)d_in[7];
    const float* kvw = (const float*)d_in[8];
    const float* kvb = (const float*)d_in[9];
    const float* rpb = (const float*)d_in[10];
    const float* pw  = (const float*)d_in[11];
    const float* pb  = (const float*)d_in[12];
    const float* n2g = (const float*)d_in[13];
    const float* n2b = (const float*)d_in[14];
    const float* f1w = (const float*)d_in[15];
    const float* f1b = (const float*)d_in[16];
    const float* f2w = (const float*)d_in[17];
    const float* f2b = (const float*)d_in[18];
    float* out = (float*)d_out;

    cvt_all<<<(Cc * MLPH + 255) / 256, 256>>>(qw, kvw, pw, f1w, f2w);
    ln1_kernel<<<T / 8, 256>>>(x, v, n1g, n1b, nvg, nvb);
    gemm_bf16<128, 0><<<dim3(T / 128, 2), 256>>>(qb, nullptr, nullptr);       // q
    gemm_bf16<128, 1><<<dim3(T / 128, 4), 256>>>(kvb, nullptr, nullptr);      // k,v
    attn_kernel<<<NWIN, 128>>>(rpb);
    gemm_bf16<128, 2><<<dim3(T / 128, 2), 256>>>(pb, x, nullptr);             // proj + residual
    ln2_kernel<<<T / 8, 256>>>(n2g, n2b);
    gemm_bf16<128, 3><<<dim3(T / 128, 8), 256>>>(f1b, nullptr, nullptr);      // fc1 + gelu
    gemm_bf16<512, 4><<<dim3(T / 128, 2), 256>>>(f2b, nullptr, out);          // fc2 + residual
}

// round 5
// speedup vs baseline: 2.6850x; 1.0239x over previous
#include <cuda_runtime.h>
#include <cuda_bf16.h>
#include <cstdint>

// ---------------- problem constants ----------------
constexpr int Bsz   = 16;
constexpr int Hdim  = 112;
constexpr int Wdim  = 112;
constexpr int Cc    = 128;
constexpr int HEADS = 4;
constexpr int HD    = 32;
constexpr int WS    = 7;
constexpr int L     = Hdim * Wdim;        // 12544
constexpr int T     = Bsz * L;            // 200704
constexpr int NTOK  = WS * WS;            // 49
constexpr int WPB   = (Hdim / WS) * (Wdim / WS);  // 256
constexpr int NWIN  = Bsz * WPB;          // 4096
constexpr int MLPH  = 512;
constexpr float SCALE = 0.17677669529663687f;
constexpr float EPS   = 1e-5f;

// ---------------- device scratch ----------------
__device__ __align__(16) __nv_bfloat16 g_xn[T * Cc];
__device__ __align__(16) __nv_bfloat16 g_vn[T * Cc];
__device__ __align__(16) __nv_bfloat16 g_q [T * Cc];
__device__ __align__(16) __nv_bfloat16 g_k [T * Cc];
__device__ __align__(16) __nv_bfloat16 g_v [T * Cc];
__device__ __align__(16) __nv_bfloat16 g_ao[T * Cc];
__device__ __align__(16) float         g_xo[T * Cc];
__device__ __align__(16) __nv_bfloat16 g_xon[T * Cc];
__device__ __align__(16) __nv_bfloat16 g_h1[(size_t)T * MLPH];
__device__ __align__(16) __nv_bfloat16 g_qw [Cc * Cc];
__device__ __align__(16) __nv_bfloat16 g_kvw[2 * Cc * Cc];
__device__ __align__(16) __nv_bfloat16 g_pw [Cc * Cc];
__device__ __align__(16) __nv_bfloat16 g_f1w[MLPH * Cc];
__device__ __align__(16) __nv_bfloat16 g_f2w[Cc * MLPH];

// ---------------- helpers ----------------
__device__ __forceinline__ uint32_t s2u(const void* p) {
    return (uint32_t)__cvta_generic_to_shared(p);
}
__device__ __forceinline__ void ldsm4(uint32_t& r0, uint32_t& r1, uint32_t& r2,
                                      uint32_t& r3, uint32_t addr) {
    asm volatile("ldmatrix.sync.aligned.m8n8.x4.shared.b16 {%0,%1,%2,%3},[%4];"
                 : "=r"(r0), "=r"(r1), "=r"(r2), "=r"(r3) : "r"(addr));
}
__device__ __forceinline__ void cpasync16(uint32_t dst, const void* src) {
    asm volatile("cp.async.cg.shared.global [%0], [%1], 16;" :: "r"(dst), "l"(src));
}
__device__ __forceinline__ void cpcommit() { asm volatile("cp.async.commit_group;"); }
__device__ __forceinline__ void cpwait1()  { asm volatile("cp.async.wait_group 1;"); }

__device__ __forceinline__ void mma16816(float* c, const uint32_t* a, const uint32_t* b) {
    asm volatile(
        "mma.sync.aligned.m16n8k16.row.col.f32.bf16.bf16.f32 "
        "{%0,%1,%2,%3},{%4,%5,%6,%7},{%8,%9},{%0,%1,%2,%3};"
        : "+f"(c[0]), "+f"(c[1]), "+f"(c[2]), "+f"(c[3])
        : "r"(a[0]), "r"(a[1]), "r"(a[2]), "r"(a[3]), "r"(b[0]), "r"(b[1]));
}

// ---------------- weight conversion ----------------
__global__ void cvt_all(const float* __restrict__ qw, const float* __restrict__ kvw,
                        const float* __restrict__ pw, const float* __restrict__ f1w,
                        const float* __restrict__ f2w) {
    int i = blockIdx.x * blockDim.x + threadIdx.x;
    if (i < Cc * Cc)     g_qw[i]  = __float2bfloat16(qw[i]);
    if (i < 2 * Cc * Cc) g_kvw[i] = __float2bfloat16(kvw[i]);
    if (i < Cc * Cc)     g_pw[i]  = __float2bfloat16(pw[i]);
    if (i < MLPH * Cc)   g_f1w[i] = __float2bfloat16(f1w[i]);
    if (i < Cc * MLPH)   g_f2w[i] = __float2bfloat16(f2w[i]);
}

// ---------------- warp-per-token LayerNorm ----------------
__device__ __forceinline__ void warp_red2(float& s, float& q) {
#pragma unroll
    for (int o = 16; o; o >>= 1) {
        s += __shfl_xor_sync(0xffffffffu, s, o);
        q += __shfl_xor_sync(0xffffffffu, q, o);
    }
}
__device__ __forceinline__ void ln_one(const float* __restrict__ src,
                                       const float* __restrict__ gamma,
                                       const float* __restrict__ beta,
                                       __nv_bfloat16* __restrict__ dst,
                                       int t, int wt, int lane) {
    float4 xv = ((const float4*)(src + (size_t)t * Cc))[lane];
    float s = xv.x + xv.y + xv.z + xv.w;
    float q = xv.x * xv.x + xv.y * xv.y + xv.z * xv.z + xv.w * xv.w;
    warp_red2(s, q);
    float mu = s * (1.0f / Cc);
    float var = q * (1.0f / Cc) - mu * mu;
    float r = rsqrtf(var + EPS);
    float4 g = ((const float4*)gamma)[lane];
    float4 b = ((const float4*)beta)[lane];
    __nv_bfloat162 p0 = {__float2bfloat16((xv.x - mu) * r * g.x + b.x),
                         __float2bfloat16((xv.y - mu) * r * g.y + b.y)};
    __nv_bfloat162 p1 = {__float2bfloat16((xv.z - mu) * r * g.z + b.z),
                         __float2bfloat16((xv.w - mu) * r * g.w + b.w)};
    uint2 out;
    out.x = *(uint32_t*)&p0;
    out.y = *(uint32_t*)&p1;
    *(uint2*)(dst + (size_t)wt * Cc + lane * 4) = out;
}

__global__ void __launch_bounds__(256) ln1_kernel(
    const float* __restrict__ x, const float* __restrict__ v,
    const float* __restrict__ g1, const float* __restrict__ b1,
    const float* __restrict__ gv, const float* __restrict__ bv) {
    int warp = threadIdx.x >> 5, lane = threadIdx.x & 31;
    int t = blockIdx.x * 8 + warp;
    int b = t / L, l = t - b * L;
    int row = l / Wdim, col = l - row * Wdim;
    int wy = row / WS, iy = row - wy * WS;
    int wx = col / WS, ix = col - wx * WS;
    int wt = ((b * WPB) + wy * 16 + wx) * NTOK + iy * WS + ix;
    ln_one(x, g1, b1, g_xn, t, wt, lane);
    ln_one(v, gv, bv, g_vn, t, wt, lane);
}

__global__ void __launch_bounds__(256) ln2_kernel(
    const float* __restrict__ g2, const float* __restrict__ b2) {
    int warp = threadIdx.x >> 5, lane = threadIdx.x & 31;
    int t = blockIdx.x * 8 + warp;
    ln_one(g_xo, g2, b2, g_xon, t, t, lane);
}

// ---------------- 3-stage pipelined bf16 tensor-core GEMM (128x64) ----------------
// out[M,N] = A[M,K] @ W[N,K]^T
// EPI: 0=Q  1=KV  2=PROJ(+x, scatter)  3=FC1(gelu)  4=FC2(+xo -> d_out)
template <int KD, int EPI>
__global__ void __launch_bounds__(256, 3) gemm_bf16(const float* __restrict__ bias,
                                                    const float* __restrict__ res,
                                                    float* __restrict__ outf) {
    constexpr int BM = 128, BN = 64, BK = 32, LDS = 40, NSTG = 3;
    __shared__ __nv_bfloat16 As[NSTG][BM * LDS];
    __shared__ __nv_bfloat16 Bs[NSTG][BN * LDS];

    const __nv_bfloat16* A =
        (EPI == 0) ? g_xn : (EPI == 1) ? g_vn : (EPI == 2) ? g_ao : (EPI == 3) ? g_xon : g_h1;
    const __nv_bfloat16* W =
        (EPI == 0) ? g_qw : (EPI == 1) ? g_kvw : (EPI == 2) ? g_pw : (EPI == 3) ? g_f1w : g_f2w;

    const int tid = threadIdx.x;
    const int m0 = blockIdx.x * BM, n0 = blockIdx.y * BN;
    const int warp = tid >> 5, lane = tid & 31;
    const int wm = (warp & 3) * 32;   // 4 warps over M
    const int wn = (warp >> 2) * 32;  // 2 warps over N
    const int g = lane >> 2, tg = lane & 3;

    const int ar0 = tid >> 2, ac0 = (tid & 3) * 8;
    const int ar1 = (tid + 256) >> 2, ac1 = ((tid + 256) & 3) * 8;

    float acc[2][4][4];
#pragma unroll
    for (int a = 0; a < 2; a++)
#pragma unroll
        for (int b = 0; b < 4; b++)
#pragma unroll
            for (int c = 0; c < 4; c++) acc[a][b][c] = 0.0f;

    auto load_tiles = [&](int buf, int k0) {
        cpasync16(s2u(&As[buf][ar0 * LDS + ac0]), A + (size_t)(m0 + ar0) * KD + k0 + ac0);
        cpasync16(s2u(&As[buf][ar1 * LDS + ac1]), A + (size_t)(m0 + ar1) * KD + k0 + ac1);
        cpasync16(s2u(&Bs[buf][ar0 * LDS + ac0]), W + (size_t)(n0 + ar0) * KD + k0 + ac0);
    };

    const int a_row = wm + (lane & 15);
    const int a_cb  = (lane >> 4) * 8;
    const int b_row = wn + ((lane >> 4) << 3) + (lane & 7);
    const int b_cb  = ((lane >> 3) & 1) * 8;

    constexpr int NK = KD / BK;   // >= 4 for all our shapes
    load_tiles(0, 0);
    cpcommit();
    load_tiles(1, BK);
    cpcommit();

    int buf = 0;
    for (int kt = 0; kt < NK; kt++) {
        cpwait1();            // tile kt resident; tile kt+1 may still be in flight
        __syncthreads();      // all warps done reading stage (kt+2)%3 from iter kt-1
        if (kt + 2 < NK) load_tiles((kt + 2) % NSTG, (kt + 2) * BK);
        cpcommit();           // commit (possibly empty) keeps group accounting uniform
#pragma unroll
        for (int kh = 0; kh < 2; kh++) {
            uint32_t a[2][4];
#pragma unroll
            for (int mi = 0; mi < 2; mi++) {
                uint32_t addr = s2u(&As[buf][(a_row + mi * 16) * LDS + kh * 16 + a_cb]);
                ldsm4(a[mi][0], a[mi][1], a[mi][2], a[mi][3], addr);
            }
            uint32_t b[2][4];
#pragma unroll
            for (int nj = 0; nj < 2; nj++) {
                uint32_t addr = s2u(&Bs[buf][(b_row + nj * 16) * LDS + kh * 16 + b_cb]);
                ldsm4(b[nj][0], b[nj][1], b[nj][2], b[nj][3], addr);
            }
#pragma unroll
            for (int mi = 0; mi < 2; mi++)
#pragma unroll
                for (int ni = 0; ni < 4; ni++) {
                    uint32_t bb[2] = {b[ni >> 1][(ni & 1) * 2], b[ni >> 1][(ni & 1) * 2 + 1]};
                    mma16816(acc[mi][ni], a[mi], bb);
                }
        }
        buf = (buf + 1 == NSTG) ? 0 : buf + 1;
    }

    // ----- epilogue -----
#pragma unroll
    for (int mi = 0; mi < 2; mi++)
#pragma unroll
        for (int rr = 0; rr < 2; rr++) {
            int row = m0 + wm + mi * 16 + g + rr * 8;
            int trow = row;
            if (EPI == 2) {
                int win = row / NTOK, n = row - win * NTOK;
                int b = win >> 8, wr = win & 255;
                int wy = wr >> 4, wx = wr & 15;
                int iy = n / WS, ix = n - iy * WS;
                trow = b * L + (wy * WS + iy) * Wdim + wx * WS + ix;
            }
#pragma unroll
            for (int ni = 0; ni < 4; ni++)
#pragma unroll
                for (int cc = 0; cc < 2; cc++) {
                    int col = n0 + wn + ni * 8 + tg * 2 + cc;
                    float vacc = acc[mi][ni][rr * 2 + cc];
                    if (EPI == 0) {
                        g_q[(size_t)row * Cc + col] =
                            __float2bfloat16((vacc + bias[col]) * SCALE);
                    } else if (EPI == 1) {
                        float v2 = vacc + bias[col];
                        if (col < Cc)
                            g_k[(size_t)row * Cc + col] = __float2bfloat16(v2);
                        else
                            g_v[(size_t)row * Cc + (col - Cc)] = __float2bfloat16(v2);
                    } else if (EPI == 2) {
                        size_t oi = (size_t)trow * Cc + col;
                        g_xo[oi] = vacc + bias[col] + res[oi];
                    } else if (EPI == 3) {
                        float v2 = vacc + bias[col];
                        float ge = 0.5f * v2 * (1.0f + erff(v2 * 0.70710678118654752f));
                        g_h1[(size_t)row * MLPH + col] = __float2bfloat16(ge);
                    } else {
                        size_t oi = (size_t)row * Cc + col;
                        outf[oi] = vacc + bias[col] + g_xo[oi];
                    }
                }
        }
}

// ---------------- tensor-core windowed attention ----------------
__global__ void __launch_bounds__(128) attn_kernel(const float* __restrict__ rpb) {
    constexpr int SST = 136;
    __shared__ __nv_bfloat16 sK[64 * SST];
    __shared__ __nv_bfloat16 sV[64 * SST];
    __shared__ float sb[HEADS * 169];

    const int win = blockIdx.x;
    const int tid = threadIdx.x, warp = tid >> 5, lane = tid & 31;
    const int g = lane >> 2, tg = lane & 3;
    const size_t base = (size_t)win * NTOK * Cc;

    for (int i = tid; i < 49 * 16; i += 128) {
        int r = i >> 4, cb = (i & 15) * 8;
        *(uint4*)&sK[r * SST + cb] = *(const uint4*)(g_k + base + (size_t)r * Cc + cb);
        *(uint4*)&sV[r * SST + cb] = *(const uint4*)(g_v + base + (size_t)r * Cc + cb);
    }
    for (int i = tid; i < 15 * 16; i += 128) {
        int r = 49 + (i >> 4), cb = (i & 15) * 8;
        *(uint4*)&sV[r * SST + cb] = make_uint4(0, 0, 0, 0);
    }
    for (int i = lane; i < 169; i += 32) sb[warp * 169 + i] = rpb[i * HEADS + warp];
    __syncthreads();

    const int hc = warp * HD;
    const float* sbh = &sb[warp * 169];

    uint32_t kb[7][2][2];
#pragma unroll
    for (int nt = 0; nt < 7; nt++)
#pragma unroll
        for (int kh = 0; kh < 2; kh++) {
            const __nv_bfloat16* p = &sK[(nt * 8 + g) * SST + hc + kh * 16 + tg * 2];
            kb[nt][kh][0] = *(const uint32_t*)p;
            kb[nt][kh][1] = *(const uint32_t*)(p + 8);
        }
    uint32_t vb[4][4][2];
#pragma unroll
    for (int kt = 0; kt < 4; kt++)
#pragma unroll
        for (int nd = 0; nd < 4; nd++) {
            int k0 = kt * 16 + tg * 2;
            int c = hc + nd * 8 + g;
            __nv_bfloat162 b0 = {sV[k0 * SST + c], sV[(k0 + 1) * SST + c]};
            __nv_bfloat162 b1 = {sV[(k0 + 8) * SST + c], sV[(k0 + 9) * SST + c]};
            vb[kt][nd][0] = *(uint32_t*)&b0;
            vb[kt][nd][1] = *(uint32_t*)&b1;
        }

#pragma unroll
    for (int mt = 0; mt < 4; mt++) {
        uint32_t qa[2][4];
        int q0 = win * NTOK + mt * 16 + g;
        int q1 = q0 + 8;
        int q0c = q0 < T ? q0 : T - 1;
        int q1c = q1 < T ? q1 : T - 1;
#pragma unroll
        for (int kh = 0; kh < 2; kh++) {
            const __nv_bfloat16* p0 = g_q + (size_t)q0c * Cc + hc + kh * 16 + tg * 2;
            const __nv_bfloat16* p1 = g_q + (size_t)q1c * Cc + hc + kh * 16 + tg * 2;
            qa[kh][0] = *(const uint32_t*)p0;
            qa[kh][1] = *(const uint32_t*)p1;
            qa[kh][2] = *(const uint32_t*)(p0 + 8);
            qa[kh][3] = *(const uint32_t*)(p1 + 8);
        }

        float s[7][4];
#pragma unroll
        for (int nt = 0; nt < 7; nt++)
#pragma unroll
            for (int c = 0; c < 4; c++) s[nt][c] = 0.0f;
#pragma unroll
        for (int kh = 0; kh < 2; kh++)
#pragma unroll
            for (int nt = 0; nt < 7; nt++) mma16816(s[nt], qa[kh], kb[nt][kh]);

        uint32_t pa[4][4];
#pragma unroll
        for (int rr = 0; rr < 2; rr++) {
            int q = mt * 16 + g + rr * 8;
            int qq = q < NTOK ? q : NTOK - 1;
            int qy = qq / WS, qx = qq - qy * WS;
            float ev[14];
            float mx = -1e30f;
#pragma unroll
            for (int nt = 0; nt < 7; nt++)
#pragma unroll
                for (int cc = 0; cc < 2; cc++) {
                    int key = nt * 8 + tg * 2 + cc;
                    float v = s[nt][rr * 2 + cc];
                    if (key < NTOK) {
                        int ky = key / WS, kx = key - ky * WS;
                        v += sbh[(qy - ky + 6) * 13 + (qx - kx + 6)];
                        mx = fmaxf(mx, v);
                    }
                    ev[nt * 2 + cc] = v;
                }
            mx = fmaxf(mx, __shfl_xor_sync(0xffffffffu, mx, 1));
            mx = fmaxf(mx, __shfl_xor_sync(0xffffffffu, mx, 2));
            float sum = 0.0f;
#pragma unroll
            for (int j = 0; j < 14; j++) {
                int key = (j >> 1) * 8 + tg * 2 + (j & 1);
                float e = (key < NTOK) ? __expf(ev[j] - mx) : 0.0f;
                ev[j] = e;
                sum += e;
            }
            sum += __shfl_xor_sync(0xffffffffu, sum, 1);
            sum += __shfl_xor_sync(0xffffffffu, sum, 2);
            float inv = 1.0f / sum;
#pragma unroll
            for (int kt = 0; kt < 4; kt++) {
                int ntA = 2 * kt, ntB = 2 * kt + 1;
                __nv_bfloat162 pA = __float22bfloat162_rn(
                    make_float2(ev[ntA * 2] * inv, ev[ntA * 2 + 1] * inv));
                pa[kt][rr] = *(uint32_t*)&pA;
                if (ntB < 7) {
                    __nv_bfloat162 pB = __float22bfloat162_rn(
                        make_float2(ev[ntB * 2] * inv, ev[ntB * 2 + 1] * inv));
                    pa[kt][2 + rr] = *(uint32_t*)&pB;
                } else {
                    pa[kt][2 + rr] = 0u;
                }
            }
        }

        float o[4][4];
#pragma unroll
        for (int nd = 0; nd < 4; nd++)
#pragma unroll
            for (int c = 0; c < 4; c++) o[nd][c] = 0.0f;
#pragma unroll
        for (int kt = 0; kt < 4; kt++)
#pragma unroll
            for (int nd = 0; nd < 4; nd++) mma16816(o[nd], pa[kt], vb[kt][nd]);

#pragma unroll
        for (int rr = 0; rr < 2; rr++) {
            int q = mt * 16 + g + rr * 8;
            if (q < NTOK) {
#pragma unroll
                for (int nd = 0; nd < 4; nd++) {
                    __nv_bfloat162 p2 = __float22bfloat162_rn(
                        make_float2(o[nd][rr * 2], o[nd][rr * 2 + 1]));
                    *(uint32_t*)(g_ao + base + (size_t)q * Cc + hc + nd * 8 + tg * 2) =
                        *(uint32_t*)&p2;
                }
            }
        }
    }
}

// ---------------- launch ----------------
extern "C" void kernel_launch(void* const* d_in, const int* in_sizes, int n_in,
                              void* d_out, int out_size) {
    const float* x   = (const float*)d_in[0];
    const float* v   = (const float*)d_in[1];
    const float* n1g = (const float*)d_in[2];
    const float* n1b = (const float*)d_in[3];
    const float* nvg = (const float*)d_in[4];
    const float* nvb = (const float*)d_in[5];
    const float* qw  = (const float*)d_in[6];
    const float* qb  = (const float*)d_in[7];
    const float* kvw = (const float*)d_in[8];
    const float* kvb = (const float*)d_in[9];
    const float* rpb = (const float*)d_in[10];
    const float* pw  = (const float*)d_in[11];
    const float* pb  = (const float*)d_in[12];
    const float* n2g = (const float*)d_in[13];
    const float* n2b = (const float*)d_in[14];
    const float* f1w = (const float*)d_in[15];
    const float* f1b = (const float*)d_in[16];
    const float* f2w = (const float*)d_in[17];
    const float* f2b = (const float*)d_in[18];
    float* out = (float*)d_out;

    cvt_all<<<(Cc * MLPH + 255) / 256, 256>>>(qw, kvw, pw, f1w, f2w);
    ln1_kernel<<<T / 8, 256>>>(x, v, n1g, n1b, nvg, nvb);
    gemm_bf16<128, 0><<<dim3(T / 128, 2), 256>>>(qb, nullptr, nullptr);       // q
    gemm_bf16<128, 1><<<dim3(T / 128, 4), 256>>>(kvb, nullptr, nullptr);      // k,v
    attn_kernel<<<NWIN, 128>>>(rpb);
    gemm_bf16<128, 2><<<dim3(T / 128, 2), 256>>>(pb, x, nullptr);             // proj + residual
    ln2_kernel<<<T / 8, 256>>>(n2g, n2b);
    gemm_bf16<128, 3><<<dim3(T / 128, 8), 256>>>(f1b, nullptr, nullptr);      // fc1 + gelu
    gemm_bf16<512, 4><<<dim3(T / 128, 2), 256>>>(f2b, nullptr, out);          // fc2 + residual
}

// round 6
// speedup vs baseline: 2.8921x; 1.0772x over previous
#include <cuda_runtime.h>
#include <cuda_bf16.h>
#include <cstdint>

// ---------------- problem constants ----------------
constexpr int Bsz   = 16;
constexpr int Hdim  = 112;
constexpr int Wdim  = 112;
constexpr int Cc    = 128;
constexpr int HEADS = 4;
constexpr int HD    = 32;
constexpr int WS    = 7;
constexpr int L     = Hdim * Wdim;        // 12544
constexpr int T     = Bsz * L;            // 200704
constexpr int NTOK  = WS * WS;            // 49
constexpr int WPB   = (Hdim / WS) * (Wdim / WS);  // 256
constexpr int NWIN  = Bsz * WPB;          // 4096
constexpr int MLPH  = 512;
constexpr float SCALE = 0.17677669529663687f;
constexpr float EPS   = 1e-5f;

// ---------------- device scratch ----------------
__device__ __align__(16) __nv_bfloat16 g_xn[T * Cc];
__device__ __align__(16) __nv_bfloat16 g_vn[T * Cc];
__device__ __align__(16) __nv_bfloat16 g_q [T * Cc];
__device__ __align__(16) __nv_bfloat16 g_k [T * Cc];
__device__ __align__(16) __nv_bfloat16 g_v [T * Cc];
__device__ __align__(16) __nv_bfloat16 g_ao[T * Cc];
__device__ __align__(16) float         g_xo[T * Cc];
__device__ __align__(16) __nv_bfloat16 g_xon[T * Cc];
__device__ __align__(16) __nv_bfloat16 g_h1[(size_t)T * MLPH];
__device__ __align__(16) __nv_bfloat16 g_qw [Cc * Cc];
__device__ __align__(16) __nv_bfloat16 g_kvw[2 * Cc * Cc];
__device__ __align__(16) __nv_bfloat16 g_pw [Cc * Cc];
__device__ __align__(16) __nv_bfloat16 g_f1w[MLPH * Cc];
__device__ __align__(16) __nv_bfloat16 g_f2w[Cc * MLPH];

// ---------------- helpers ----------------
__device__ __forceinline__ uint32_t s2u(const void* p) {
    return (uint32_t)__cvta_generic_to_shared(p);
}
__device__ __forceinline__ void ldsm4(uint32_t& r0, uint32_t& r1, uint32_t& r2,
                                      uint32_t& r3, uint32_t addr) {
    asm volatile("ldmatrix.sync.aligned.m8n8.x4.shared.b16 {%0,%1,%2,%3},[%4];"
                 : "=r"(r0), "=r"(r1), "=r"(r2), "=r"(r3) : "r"(addr));
}
__device__ __forceinline__ void cpasync16(uint32_t dst, const void* src) {
    asm volatile("cp.async.cg.shared.global [%0], [%1], 16;" :: "r"(dst), "l"(src));
}
__device__ __forceinline__ void cpcommit() { asm volatile("cp.async.commit_group;"); }
__device__ __forceinline__ void cpwait0()  { asm volatile("cp.async.wait_group 0;"); }

__device__ __forceinline__ void mma16816(float* c, const uint32_t* a, const uint32_t* b) {
    asm volatile(
        "mma.sync.aligned.m16n8k16.row.col.f32.bf16.bf16.f32 "
        "{%0,%1,%2,%3},{%4,%5,%6,%7},{%8,%9},{%0,%1,%2,%3};"
        : "+f"(c[0]), "+f"(c[1]), "+f"(c[2]), "+f"(c[3])
        : "r"(a[0]), "r"(a[1]), "r"(a[2]), "r"(a[3]), "r"(b[0]), "r"(b[1]));
}

// ---------------- weight conversion ----------------
__global__ void cvt_all(const float* __restrict__ qw, const float* __restrict__ kvw,
                        const float* __restrict__ pw, const float* __restrict__ f1w,
                        const float* __restrict__ f2w) {
    int i = blockIdx.x * blockDim.x + threadIdx.x;
    if (i < Cc * Cc)     g_qw[i]  = __float2bfloat16(qw[i]);
    if (i < 2 * Cc * Cc) g_kvw[i] = __float2bfloat16(kvw[i]);
    if (i < Cc * Cc)     g_pw[i]  = __float2bfloat16(pw[i]);
    if (i < MLPH * Cc)   g_f1w[i] = __float2bfloat16(f1w[i]);
    if (i < Cc * MLPH)   g_f2w[i] = __float2bfloat16(f2w[i]);
}

// ---------------- warp-per-token LayerNorm ----------------
__device__ __forceinline__ void warp_red2(float& s, float& q) {
#pragma unroll
    for (int o = 16; o; o >>= 1) {
        s += __shfl_xor_sync(0xffffffffu, s, o);
        q += __shfl_xor_sync(0xffffffffu, q, o);
    }
}
__device__ __forceinline__ void ln_one(const float* __restrict__ src,
                                       const float* __restrict__ gamma,
                                       const float* __restrict__ beta,
                                       __nv_bfloat16* __restrict__ dst,
                                       int t, int wt, int lane) {
    float4 xv = ((const float4*)(src + (size_t)t * Cc))[lane];
    float s = xv.x + xv.y + xv.z + xv.w;
    float q = xv.x * xv.x + xv.y * xv.y + xv.z * xv.z + xv.w * xv.w;
    warp_red2(s, q);
    float mu = s * (1.0f / Cc);
    float var = q * (1.0f / Cc) - mu * mu;
    float r = rsqrtf(var + EPS);
    float4 g = ((const float4*)gamma)[lane];
    float4 b = ((const float4*)beta)[lane];
    __nv_bfloat162 p0 = {__float2bfloat16((xv.x - mu) * r * g.x + b.x),
                         __float2bfloat16((xv.y - mu) * r * g.y + b.y)};
    __nv_bfloat162 p1 = {__float2bfloat16((xv.z - mu) * r * g.z + b.z),
                         __float2bfloat16((xv.w - mu) * r * g.w + b.w)};
    uint2 out;
    out.x = *(uint32_t*)&p0;
    out.y = *(uint32_t*)&p1;
    *(uint2*)(dst + (size_t)wt * Cc + lane * 4) = out;
}

__global__ void __launch_bounds__(256) ln1_kernel(
    const float* __restrict__ x, const float* __restrict__ v,
    const float* __restrict__ g1, const float* __restrict__ b1,
    const float* __restrict__ gv, const float* __restrict__ bv) {
    int warp = threadIdx.x >> 5, lane = threadIdx.x & 31;
    int t = blockIdx.x * 8 + warp;
    int b = t / L, l = t - b * L;
    int row = l / Wdim, col = l - row * Wdim;
    int wy = row / WS, iy = row - wy * WS;
    int wx = col / WS, ix = col - wx * WS;
    int wt = ((b * WPB) + wy * 16 + wx) * NTOK + iy * WS + ix;
    ln_one(x, g1, b1, g_xn, t, wt, lane);
    ln_one(v, gv, bv, g_vn, t, wt, lane);
}

__global__ void __launch_bounds__(256) ln2_kernel(
    const float* __restrict__ g2, const float* __restrict__ b2) {
    int warp = threadIdx.x >> 5, lane = threadIdx.x & 31;
    int t = blockIdx.x * 8 + warp;
    ln_one(g_xo, g2, b2, g_xon, t, t, lane);
}

// ---------------- full-K-resident bf16 tensor-core GEMM (128x64) ----------------
// out[M,N] = A[M,K] @ W[N,K]^T, K processed in resident chunks of 128.
// smem: A 128x128 + B 64x128 bf16, XOR-swizzled 16B chunks = 48KB exactly.
// EPI: 0=Q  1=KV  2=PROJ(+x, scatter)  3=FC1(gelu)  4=FC2(+xo -> d_out)
template <int KD, int EPI>
__global__ void __launch_bounds__(256, 3) gemm_bf16(const float* __restrict__ bias,
                                                    const float* __restrict__ res,
                                                    float* __restrict__ outf) {
    __shared__ __nv_bfloat16 sA[128 * 128];
    __shared__ __nv_bfloat16 sB[64 * 128];

    const __nv_bfloat16* A =
        (EPI == 0) ? g_xn : (EPI == 1) ? g_vn : (EPI == 2) ? g_ao : (EPI == 3) ? g_xon : g_h1;
    const __nv_bfloat16* W =
        (EPI == 0) ? g_qw : (EPI == 1) ? g_kvw : (EPI == 2) ? g_pw : (EPI == 3) ? g_f1w : g_f2w;

    const int tid = threadIdx.x;
    const int m0 = blockIdx.x * 128, n0 = blockIdx.y * 64;
    const int warp = tid >> 5, lane = tid & 31;
    const int wm = (warp & 3) * 32;   // 4 warps over M
    const int wn = (warp >> 2) * 32;  // 2 warps over N
    const int g = lane >> 2, tg = lane & 3;

    const uint32_t sA_u = s2u(sA), sB_u = s2u(sB);

    float acc[2][4][4];
#pragma unroll
    for (int a = 0; a < 2; a++)
#pragma unroll
        for (int b = 0; b < 4; b++)
#pragma unroll
            for (int c = 0; c < 4; c++) acc[a][b][c] = 0.0f;

    // ldsm lane addressing (bytes): row*256 + swizzled_chunk*16
    const int a_row = wm + (lane & 15);
    const int a_ch  = lane >> 4;              // 0/1 -> k-halfchunk
    const int b_row = wn + ((lane >> 4) << 3) + (lane & 7);
    const int b_ch  = (lane >> 3) & 1;

    constexpr int NKC = KD / 128;
    for (int kc = 0; kc < NKC; kc++) {
        if (kc) __syncthreads();     // done reading previous chunk
        const int k0 = kc * 128;
        // burst load: A 2048 chunks, B 1024 chunks of 16B
#pragma unroll
        for (int i = 0; i < 8; i++) {
            int idx = tid + i * 256;
            int row = idx >> 4, c = idx & 15;
            uint32_t off = ((uint32_t)row << 8) + (uint32_t)((c ^ (row & 7)) << 4);
            cpasync16(sA_u + off, A + (size_t)(m0 + row) * KD + k0 + c * 8);
        }
#pragma unroll
        for (int i = 0; i < 4; i++) {
            int idx = tid + i * 256;
            int row = idx >> 4, c = idx & 15;
            uint32_t off = ((uint32_t)row << 8) + (uint32_t)((c ^ (row & 7)) << 4);
            cpasync16(sB_u + off, W + (size_t)(n0 + row) * KD + k0 + c * 8);
        }
        cpcommit();
        cpwait0();
        __syncthreads();

#pragma unroll
        for (int kh = 0; kh < 8; kh++) {
            uint32_t a[2][4];
#pragma unroll
            for (int mi = 0; mi < 2; mi++) {
                int row = a_row + mi * 16;
                int ch = (2 * kh + a_ch) ^ (row & 7);
                ldsm4(a[mi][0], a[mi][1], a[mi][2], a[mi][3],
                      sA_u + ((uint32_t)row << 8) + (uint32_t)(ch << 4));
            }
            uint32_t b[2][4];
#pragma unroll
            for (int nj = 0; nj < 2; nj++) {
                int row = b_row + nj * 16;
                int ch = (2 * kh + b_ch) ^ (row & 7);
                ldsm4(b[nj][0], b[nj][1], b[nj][2], b[nj][3],
                      sB_u + ((uint32_t)row << 8) + (uint32_t)(ch << 4));
            }
#pragma unroll
            for (int mi = 0; mi < 2; mi++)
#pragma unroll
                for (int ni = 0; ni < 4; ni++) {
                    uint32_t bb[2] = {b[ni >> 1][(ni & 1) * 2], b[ni >> 1][(ni & 1) * 2 + 1]};
                    mma16816(acc[mi][ni], a[mi], bb);
                }
        }
    }

    // ----- epilogue -----
#pragma unroll
    for (int mi = 0; mi < 2; mi++)
#pragma unroll
        for (int rr = 0; rr < 2; rr++) {
            int row = m0 + wm + mi * 16 + g + rr * 8;
            int trow = row;
            if (EPI == 2) {
                int win = row / NTOK, n = row - win * NTOK;
                int b = win >> 8, wr = win & 255;
                int wy = wr >> 4, wx = wr & 15;
                int iy = n / WS, ix = n - iy * WS;
                trow = b * L + (wy * WS + iy) * Wdim + wx * WS + ix;
            }
#pragma unroll
            for (int ni = 0; ni < 4; ni++)
#pragma unroll
                for (int cc = 0; cc < 2; cc++) {
                    int col = n0 + wn + ni * 8 + tg * 2 + cc;
                    float vacc = acc[mi][ni][rr * 2 + cc] + __ldg(bias + col);
                    if (EPI == 0) {
                        g_q[(size_t)row * Cc + col] = __float2bfloat16(vacc * SCALE);
                    } else if (EPI == 1) {
                        if (col < Cc)
                            g_k[(size_t)row * Cc + col] = __float2bfloat16(vacc);
                        else
                            g_v[(size_t)row * Cc + (col - Cc)] = __float2bfloat16(vacc);
                    } else if (EPI == 2) {
                        size_t oi = (size_t)trow * Cc + col;
                        g_xo[oi] = vacc + res[oi];
                    } else if (EPI == 3) {
                        float ge = 0.5f * vacc * (1.0f + erff(vacc * 0.70710678118654752f));
                        g_h1[(size_t)row * MLPH + col] = __float2bfloat16(ge);
                    } else {
                        size_t oi = (size_t)row * Cc + col;
                        outf[oi] = vacc + g_xo[oi];
                    }
                }
        }
}

// ---------------- tensor-core windowed attention ----------------
__global__ void __launch_bounds__(128) attn_kernel(const float* __restrict__ rpb) {
    constexpr int SST = 136;
    __shared__ __nv_bfloat16 sK[64 * SST];
    __shared__ __nv_bfloat16 sV[64 * SST];
    __shared__ float sb[HEADS * 169];

    const int win = blockIdx.x;
    const int tid = threadIdx.x, warp = tid >> 5, lane = tid & 31;
    const int g = lane >> 2, tg = lane & 3;
    const size_t base = (size_t)win * NTOK * Cc;

    for (int i = tid; i < 49 * 16; i += 128) {
        int r = i >> 4, cb = (i & 15) * 8;
        *(uint4*)&sK[r * SST + cb] = *(const uint4*)(g_k + base + (size_t)r * Cc + cb);
        *(uint4*)&sV[r * SST + cb] = *(const uint4*)(g_v + base + (size_t)r * Cc + cb);
    }
    for (int i = tid; i < 15 * 16; i += 128) {
        int r = 49 + (i >> 4), cb = (i & 15) * 8;
        *(uint4*)&sV[r * SST + cb] = make_uint4(0, 0, 0, 0);
    }
    for (int i = lane; i < 169; i += 32) sb[warp * 169 + i] = rpb[i * HEADS + warp];
    __syncthreads();

    const int hc = warp * HD;
    const float* sbh = &sb[warp * 169];

    uint32_t kb[7][2][2];
#pragma unroll
    for (int nt = 0; nt < 7; nt++)
#pragma unroll
        for (int kh = 0; kh < 2; kh++) {
            const __nv_bfloat16* p = &sK[(nt * 8 + g) * SST + hc + kh * 16 + tg * 2];
            kb[nt][kh][0] = *(const uint32_t*)p;
            kb[nt][kh][1] = *(const uint32_t*)(p + 8);
        }
    uint32_t vb[4][4][2];
#pragma unroll
    for (int kt = 0; kt < 4; kt++)
#pragma unroll
        for (int nd = 0; nd < 4; nd++) {
            int k0 = kt * 16 + tg * 2;
            int c = hc + nd * 8 + g;
            __nv_bfloat162 b0 = {sV[k0 * SST + c], sV[(k0 + 1) * SST + c]};
            __nv_bfloat162 b1 = {sV[(k0 + 8) * SST + c], sV[(k0 + 9) * SST + c]};
            vb[kt][nd][0] = *(uint32_t*)&b0;
            vb[kt][nd][1] = *(uint32_t*)&b1;
        }

#pragma unroll
    for (int mt = 0; mt < 4; mt++) {
        uint32_t qa[2][4];
        int q0 = win * NTOK + mt * 16 + g;
        int q1 = q0 + 8;
        int q0c = q0 < T ? q0 : T - 1;
        int q1c = q1 < T ? q1 : T - 1;
#pragma unroll
        for (int kh = 0; kh < 2; kh++) {
            const __nv_bfloat16* p0 = g_q + (size_t)q0c * Cc + hc + kh * 16 + tg * 2;
            const __nv_bfloat16* p1 = g_q + (size_t)q1c * Cc + hc + kh * 16 + tg * 2;
            qa[kh][0] = *(const uint32_t*)p0;
            qa[kh][1] = *(const uint32_t*)p1;
            qa[kh][2] = *(const uint32_t*)(p0 + 8);
            qa[kh][3] = *(const uint32_t*)(p1 + 8);
        }

        float s[7][4];
#pragma unroll
        for (int nt = 0; nt < 7; nt++)
#pragma unroll
            for (int c = 0; c < 4; c++) s[nt][c] = 0.0f;
#pragma unroll
        for (int kh = 0; kh < 2; kh++)
#pragma unroll
            for (int nt = 0; nt < 7; nt++) mma16816(s[nt], qa[kh], kb[nt][kh]);

        uint32_t pa[4][4];
#pragma unroll
        for (int rr = 0; rr < 2; rr++) {
            int q = mt * 16 + g + rr * 8;
            int qq = q < NTOK ? q : NTOK - 1;
            int qy = qq / WS, qx = qq - qy * WS;
            float ev[14];
            float mx = -1e30f;
#pragma unroll
            for (int nt = 0; nt < 7; nt++)
#pragma unroll
                for (int cc = 0; cc < 2; cc++) {
                    int key = nt * 8 + tg * 2 + cc;
                    float v = s[nt][rr * 2 + cc];
                    if (key < NTOK) {
                        int ky = key / WS, kx = key - ky * WS;
                        v += sbh[(qy - ky + 6) * 13 + (qx - kx + 6)];
                        mx = fmaxf(mx, v);
                    }
                    ev[nt * 2 + cc] = v;
                }
            mx = fmaxf(mx, __shfl_xor_sync(0xffffffffu, mx, 1));
            mx = fmaxf(mx, __shfl_xor_sync(0xffffffffu, mx, 2));
            float sum = 0.0f;
#pragma unroll
            for (int j = 0; j < 14; j++) {
                int key = (j >> 1) * 8 + tg * 2 + (j & 1);
                float e = (key < NTOK) ? __expf(ev[j] - mx) : 0.0f;
                ev[j] = e;
                sum += e;
            }
            sum += __shfl_xor_sync(0xffffffffu, sum, 1);
            sum += __shfl_xor_sync(0xffffffffu, sum, 2);
            float inv = 1.0f / sum;
#pragma unroll
            for (int kt = 0; kt < 4; kt++) {
                int ntA = 2 * kt, ntB = 2 * kt + 1;
                __nv_bfloat162 pA = __float22bfloat162_rn(
                    make_float2(ev[ntA * 2] * inv, ev[ntA * 2 + 1] * inv));
                pa[kt][rr] = *(uint32_t*)&pA;
                if (ntB < 7) {
                    __nv_bfloat162 pB = __float22bfloat162_rn(
                        make_float2(ev[ntB * 2] * inv, ev[ntB * 2 + 1] * inv));
                    pa[kt][2 + rr] = *(uint32_t*)&pB;
                } else {
                    pa[kt][2 + rr] = 0u;
                }
            }
        }

        float o[4][4];
#pragma unroll
        for (int nd = 0; nd < 4; nd++)
#pragma unroll
            for (int c = 0; c < 4; c++) o[nd][c] = 0.0f;
#pragma unroll
        for (int kt = 0; kt < 4; kt++)
#pragma unroll
            for (int nd = 0; nd < 4; nd++) mma16816(o[nd], pa[kt], vb[kt][nd]);

#pragma unroll
        for (int rr = 0; rr < 2; rr++) {
            int q = mt * 16 + g + rr * 8;
            if (q < NTOK) {
#pragma unroll
                for (int nd = 0; nd < 4; nd++) {
                    __nv_bfloat162 p2 = __float22bfloat162_rn(
                        make_float2(o[nd][rr * 2], o[nd][rr * 2 + 1]));
                    *(uint32_t*)(g_ao + base + (size_t)q * Cc + hc + nd * 8 + tg * 2) =
                        *(uint32_t*)&p2;
                }
            }
        }
    }
}

// ---------------- launch ----------------
extern "C" void kernel_launch(void* const* d_in, const int* in_sizes, int n_in,
                              void* d_out, int out_size) {
    const float* x   = (const float*)d_in[0];
    const float* v   = (const float*)d_in[1];
    const float* n1g = (const float*)d_in[2];
    const float* n1b = (const float*)d_in[3];
    const float* nvg = (const float*)d_in[4];
    const float* nvb = (const float*)d_in[5];
    const float* qw  = (const float*)d_in[6];
    const float* qb  = (const float*)d_in[7];
    const float* kvw = (const float*)d_in[8];
    const float* kvb = (const float*)d_in[9];
    const float* rpb = (const float*)d_in[10];
    const float* pw  = (const float*)d_in[11];
    const float* pb  = (const float*)d_in[12];
    const float* n2g = (const float*)d_in[13];
    const float* n2b = (const float*)d_in[14];
    const float* f1w = (const float*)d_in[15];
    const float* f1b = (const float*)d_in[16];
    const float* f2w = (const float*)d_in[17];
    const float* f2b = (const float*)d_in[18];
    float* out = (float*)d_out;

    cvt_all<<<(Cc * MLPH + 255) / 256, 256>>>(qw, kvw, pw, f1w, f2w);
    ln1_kernel<<<T / 8, 256>>>(x, v, n1g, n1b, nvg, nvb);
    gemm_bf16<128, 0><<<dim3(T / 128, 2), 256>>>(qb, nullptr, nullptr);       // q
    gemm_bf16<128, 1><<<dim3(T / 128, 4), 256>>>(kvb, nullptr, nullptr);      // k,v
    attn_kernel<<<NWIN, 128>>>(rpb);
    gemm_bf16<128, 2><<<dim3(T / 128, 2), 256>>>(pb, x, nullptr);             // proj + residual
    ln2_kernel<<<T / 8, 256>>>(n2g, n2b);
    gemm_bf16<128, 3><<<dim3(T / 128, 8), 256>>>(f1b, nullptr, nullptr);      // fc1 + gelu
    gemm_bf16<512, 4><<<dim3(T / 128, 2), 256>>>(f2b, nullptr, out);          // fc2 + residual
}